// round 12
// baseline (speedup 1.0000x reference)
#include <cuda_runtime.h>
#include <cuda_bf16.h>
#include <mma.h>
#include <math.h>

using namespace nvcuda;

#define MEMD 172
#define FEATD 172
#define TDD 100
#define KNB 10
#define DHD 86
#define MSGD 616          // 2*MEM + FEAT + TD
#define G3 516            // 3*MEM
#define NMAX 100000
#define NPAD 100096       // divisible by 256
#define RB 256

// padded K strides for bf16 operand buffers
#define KP_M 640
#define KP_S 192
// padded N strides for B operand buffers
#define NP_G 640
#define NP_Q 768          // 516 + 200 score cols
#define NP_S 256
#define WT_K 256

// ---------------- device scratch ----------------
__device__ int   g_lastpos[NMAX];
__device__ __nv_bfloat16 g_Mh[(size_t)NPAD * KP_M];
__device__ __nv_bfloat16 g_memh[(size_t)NPAD * KP_S];
__device__ __nv_bfloat16 g_hh[(size_t)NPAD * KP_S];
__device__ __nv_bfloat16 g_aggh[(size_t)NPAD * KP_S];
__device__ __nv_bfloat16 g_t1h[(size_t)NPAD * KP_S];
__device__ __nv_bfloat16 g_wtb[(size_t)NPAD * WT_K];
__device__ __nv_bfloat16 g_BWih[KP_M * NP_G];
__device__ __nv_bfloat16 g_BWil[KP_M * NP_G];
__device__ __nv_bfloat16 g_BWhh[KP_S * NP_G];
__device__ __nv_bfloat16 g_BWhl[KP_S * NP_G];
__device__ __nv_bfloat16 g_BQh[KP_S * NP_Q];
__device__ __nv_bfloat16 g_BQl[KP_S * NP_Q];
__device__ __nv_bfloat16 g_BVh[WT_K * 256];
__device__ __nv_bfloat16 g_BVl[WT_K * 256];
__device__ __nv_bfloat16 g_BW1ah[KP_S * NP_S];
__device__ __nv_bfloat16 g_BW1al[KP_S * NP_S];
__device__ __nv_bfloat16 g_BW1bh[KP_S * NP_S];
__device__ __nv_bfloat16 g_BW1bl[KP_S * NP_S];
__device__ __nv_bfloat16 g_BW2h[KP_S * NP_S];
__device__ __nv_bfloat16 g_BW2l[KP_S * NP_S];
__device__ float g_GI[(size_t)NMAX * G3];
__device__ float g_GH[(size_t)NMAX * G3];
__device__ float g_QKV[(size_t)NMAX * NP_Q];
__device__ float g_aggF[(size_t)NPAD * KP_S];
__device__ float g_T1[(size_t)NMAX * MEMD];
__device__ float g_emb[(size_t)NMAX * MEMD];
__device__ float g_qconst[MEMD];
__device__ float g_const2[2 * TDD];
__device__ float g_partial[RB * MEMD];

// fp32 Cody-Waite cos: q = rintf(x/2pi) exact for |q|<2^23; two-term FMA reduction.
// 2pi = c1 + c2, c1 = fp32(2pi) = 6.2831855f, c2 = -1.7484555e-7
__device__ __forceinline__ float cos_acc(float x) {
    float q = rintf(x * 0.15915494f);
    float r = fmaf(-q, 6.2831855f, x);
    r = fmaf(q, 1.7484555e-7f, r);
    return cosf(r);
}

__device__ __forceinline__ void split2(float x, __nv_bfloat16* hi, __nv_bfloat16* lo) {
    __nv_bfloat16 h = __float2bfloat16(x);
    *hi = h;
    *lo = __float2bfloat16(x - __bfloat162float(h));
}

// ---------------- prep kernels ----------------
__global__ void k_prep_wi_init(const float* __restrict__ Wi, int N) {
    int idx = blockIdx.x * blockDim.x + threadIdx.x;
    if (idx < N) g_lastpos[idx] = -1;
    if (idx < KP_M * NP_G) {
        int k = idx / NP_G, n = idx - k * NP_G;
        float v = (k < MSGD && n < G3) ? Wi[n * MSGD + k] : 0.f;
        split2(v, &g_BWih[idx], &g_BWil[idx]);
    }
}

__global__ void k_scatter(const int* __restrict__ src, const int* __restrict__ dst, int E) {
    int e = blockIdx.x * blockDim.x + threadIdx.x;
    if (e < E) {
        atomicMax(&g_lastpos[src[e]], e);
        atomicMax(&g_lastpos[dst[e]], E + e);
    }
}

__global__ void k_prep_wh(const float* __restrict__ Wh) {
    int idx = blockIdx.x * blockDim.x + threadIdx.x;
    if (idx < KP_S * NP_G) {
        int k = idx / NP_G, n = idx - k * NP_G;
        float v = (k < MEMD && n < G3) ? Wh[n * MEMD + k] : 0.f;
        split2(v, &g_BWhh[idx], &g_BWhl[idx]);
    }
}

__global__ void k_prep_qkv(const float* __restrict__ Wq, const float* __restrict__ Wk,
                           const float* __restrict__ Wv) {
    int idx = blockIdx.x * blockDim.x + threadIdx.x;
    if (idx >= KP_S * NP_Q) return;
    int k = idx / NP_Q, n = idx - k * NP_Q;
    float v = 0.f;
    if (k < MEMD) {
        if (n < G3) {
            int sel = n / MEMD, jj = n - sel * MEMD;
            const float* W = (sel == 0) ? Wq : ((sel == 1) ? Wk : Wv);
            v = W[k * MEMD + jj];
        } else if (n < G3 + 2 * TDD) {
            int j = n - G3;
            int hh = j / TDD, t = j - hh * TDD;
            const float* wq = Wq + (size_t)k * MEMD + hh * DHD;
            const float* wk2 = Wk + (size_t)(MEMD + t) * MEMD + hh * DHD;
            float s = 0.f;
            for (int d = 0; d < DHD; d++) s += wq[d] * wk2[d];
            v = s;
        }
    }
    split2(v, &g_BQh[idx], &g_BQl[idx]);
}

__global__ void k_prep_bv(const float* __restrict__ Wv) {
    int idx = blockIdx.x * blockDim.x + threadIdx.x;
    if (idx >= WT_K * 256) return;
    int kk = idx / 256, d = idx - kk * 256;
    float v = 0.f;
    if (kk < 2 * TDD && d < MEMD) {
        int hh = kk / TDD, t = kk - hh * TDD;
        if (d / DHD == hh) v = Wv[(size_t)(MEMD + t) * MEMD + d];
    }
    split2(v, &g_BVh[idx], &g_BVl[idx]);
}

__global__ void k_prep_w1(const float* __restrict__ W1) {
    int idx = blockIdx.x * blockDim.x + threadIdx.x;
    if (idx < KP_S * NP_S) {
        int k = idx / NP_S, n = idx - k * NP_S;
        float va = 0.f, vb = 0.f;
        if (k < MEMD && n < MEMD) {
            va = W1[k * MEMD + n];
            vb = W1[(MEMD + k) * MEMD + n];
        }
        split2(va, &g_BW1ah[idx], &g_BW1al[idx]);
        split2(vb, &g_BW1bh[idx], &g_BW1bl[idx]);
    }
}

__global__ void k_prep_w2(const float* __restrict__ W2) {
    int idx = blockIdx.x * blockDim.x + threadIdx.x;
    if (idx < KP_S * NP_S) {
        int k = idx / NP_S, n = idx - k * NP_S;
        float v = (k < MEMD && n < MEMD) ? W2[k * MEMD + n] : 0.f;
        split2(v, &g_BW2h[idx], &g_BW2l[idx]);
    }
}

__global__ void k_prep_qconst(const float* __restrict__ Wq, const float* __restrict__ Wk,
                              const float* __restrict__ tb) {
    __shared__ float qc[MEMD];
    int j = threadIdx.x;
    if (j < MEMD) {
        float s = 0.f;
        for (int t = 0; t < TDD; t++)
            s += cos_acc(tb[t]) * Wq[(MEMD + t) * MEMD + j];
        qc[j] = s;
        g_qconst[j] = s;
    }
    __syncthreads();
    if (j < 2 * TDD) {
        int hh = j / TDD, t = j - hh * TDD;
        const float* wk2 = Wk + (size_t)(MEMD + t) * MEMD + hh * DHD;
        float s = 0.f;
        for (int d = 0; d < DHD; d++) s += wk2[d] * qc[hh * DHD + d];
        g_const2[j] = s;
    }
}

__global__ void k_memconv(const float* __restrict__ mem, int Nn) {
    int idx = blockIdx.x * blockDim.x + threadIdx.x;
    if (idx >= NPAD * KP_S) return;
    int n = idx / KP_S, d = idx - n * KP_S;
    float v = (n < Nn && d < MEMD) ? mem[(size_t)n * MEMD + d] : 0.f;
    g_memh[idx] = __float2bfloat16(v);
}

// ---------------- build selected message matrix ----------------
__global__ void k_build_m(const float* __restrict__ mem, const float* __restrict__ lu,
                          const float* __restrict__ ts, const float* __restrict__ ef,
                          const float* __restrict__ tw, const float* __restrict__ tb,
                          const int* __restrict__ src, const int* __restrict__ dst,
                          int Nn, int E) {
    int n = blockIdx.x;
    int tid = threadIdx.x;
    __nv_bfloat16* rh = g_Mh + (size_t)n * KP_M;
    __shared__ int s_a, s_b, s_e, s_has;
    __shared__ float s_dt;
    if (tid == 0) {
        int p = (n < Nn) ? g_lastpos[n] : -1;
        if (p < 0) {
            s_has = 0;
        } else {
            s_has = 1;
            int e, a, b;
            if (p < E) { e = p;     a = src[e]; b = dst[e]; }
            else       { e = p - E; a = dst[e]; b = src[e]; }
            s_e = e; s_a = a; s_b = b;
            s_dt = ts[e] - lu[a];
        }
    }
    __syncthreads();
    if (!s_has) {
        __nv_bfloat16 z = __float2bfloat16(0.f);
        for (int i = tid; i < KP_M; i += blockDim.x) rh[i] = z;
        return;
    }
    int a = s_a, b = s_b, e = s_e;
    float dt = s_dt;
    for (int i = tid; i < KP_M; i += blockDim.x) {
        float v = 0.f;
        if (i < MEMD)                  v = mem[(size_t)a * MEMD + i];
        else if (i < 2 * MEMD)         v = mem[(size_t)b * MEMD + (i - MEMD)];
        else if (i < 2 * MEMD + FEATD) v = ef[(size_t)e * FEATD + (i - 2 * MEMD)];
        else if (i < MSGD) { int t = i - (2 * MEMD + FEATD); v = cos_acc(dt * tw[t] + tb[t]); }
        rh[i] = __float2bfloat16(v);
    }
}

// ---------------- 2-product bf16 wmma GEMM: C (+)= Ah @ (Bh + Bl) --------------------
// CTA tile 256x128, BK=32, 8 warps (2x4), warp tile 128x32 (LDSM/mma ratio 0.375 vs 0.5).
// Double-buffered smem, reg prefetch, 1 sync/iter. fp32 C, round-1 epilogue via smem
// overlay (4 phases of 64 rows), full M/N guards.
#define GBK 32
#define APADS 40
#define BPADS 136
#define CPADS 132
#define SM_A0   0
#define SM_A1   20480
#define SM_BH0  40960
#define SM_BL0  49664
#define SM_BH1  58368
#define SM_BL1  67072
#define SM_TOT  75776       // Cs overlay 64*132*4 = 33792 <= SM_TOT

__global__ __launch_bounds__(256, 1) void k_gemm2(
        const __nv_bfloat16* __restrict__ Agh, int lda,
        const __nv_bfloat16* __restrict__ Bgh, const __nv_bfloat16* __restrict__ Bgl, int ldb,
        const float* __restrict__ bias, float* __restrict__ C,
        int M, int N, int Kp, int accum, int relu) {
    extern __shared__ __align__(16) unsigned char sraw[];
    __nv_bfloat16* Abuf[2] = { (__nv_bfloat16*)(sraw + SM_A0),  (__nv_bfloat16*)(sraw + SM_A1)  };
    __nv_bfloat16* Bhb[2]  = { (__nv_bfloat16*)(sraw + SM_BH0), (__nv_bfloat16*)(sraw + SM_BH1) };
    __nv_bfloat16* Blb[2]  = { (__nv_bfloat16*)(sraw + SM_BL0), (__nv_bfloat16*)(sraw + SM_BL1) };
    float* Cs = (float*)sraw;

    int tid = threadIdx.x;
    int w = tid >> 5;
    int wm = w >> 2, wn = w & 3;        // warp grid 2 (M) x 4 (N)
    int row0 = blockIdx.y * 256;
    int col0 = blockIdx.x * 128;

    wmma::fragment<wmma::accumulator, 16, 16, 16, float> acc[8][2];
#pragma unroll
    for (int i = 0; i < 8; i++)
#pragma unroll
        for (int j = 0; j < 2; j++) wmma::fill_fragment(acc[i][j], 0.f);

    // A: one thread per row (256 rows), 32 k-elems = 4 uint4
    // B: bk = tid>>3 (32 k-rows), 16 n-elems = 2 uint4 per plane
    int bk = tid >> 3, bns = (tid & 7) * 16;
    const __nv_bfloat16* pAh = Agh + (size_t)(row0 + tid) * lda;
    const __nv_bfloat16* pBh = Bgh + (size_t)bk * ldb + col0 + bns;
    const __nv_bfloat16* pBl = Bgl + (size_t)bk * ldb + col0 + bns;
    int aoff = tid * APADS;
    int boff = bk * BPADS + bns;

    // prologue: tile 0 -> buffer 0
    {
        const uint4* qA = (const uint4*)pAh;
        uint4 a0 = qA[0], a1 = qA[1], a2 = qA[2], a3 = qA[3];
        uint4 b0 = ((const uint4*)pBh)[0], b1 = ((const uint4*)pBh)[1];
        uint4 c0 = ((const uint4*)pBl)[0], c1 = ((const uint4*)pBl)[1];
        uint4* dA = (uint4*)(Abuf[0] + aoff);
        dA[0] = a0; dA[1] = a1; dA[2] = a2; dA[3] = a3;
        ((uint4*)(Bhb[0] + boff))[0] = b0; ((uint4*)(Bhb[0] + boff))[1] = b1;
        ((uint4*)(Blb[0] + boff))[0] = c0; ((uint4*)(Blb[0] + boff))[1] = c1;
    }
    __syncthreads();

    int nIter = Kp / GBK;
    for (int it = 0; it < nIter; it++) {
        int cur = it & 1, nxt = cur ^ 1;
        bool has = (it + 1 < nIter);
        uint4 rA0, rA1, rA2, rA3, rB0, rB1, rC0, rC1;
        if (has) {
            int k1 = (it + 1) * GBK;
            const uint4* qA = (const uint4*)(pAh + k1);
            rA0 = qA[0]; rA1 = qA[1]; rA2 = qA[2]; rA3 = qA[3];
            rB0 = ((const uint4*)(pBh + (size_t)k1 * ldb))[0];
            rB1 = ((const uint4*)(pBh + (size_t)k1 * ldb))[1];
            rC0 = ((const uint4*)(pBl + (size_t)k1 * ldb))[0];
            rC1 = ((const uint4*)(pBl + (size_t)k1 * ldb))[1];
        }
        const __nv_bfloat16* As = Abuf[cur];
        const __nv_bfloat16* Bhs = Bhb[cur];
        const __nv_bfloat16* Bls = Blb[cur];
#pragma unroll
        for (int ks = 0; ks < GBK; ks += 16) {
            wmma::fragment<wmma::matrix_b, 16, 16, 16, __nv_bfloat16, wmma::row_major> bh[2], bl[2];
            wmma::load_matrix_sync(bh[0], Bhs + ks * BPADS + wn * 32,      BPADS);
            wmma::load_matrix_sync(bh[1], Bhs + ks * BPADS + wn * 32 + 16, BPADS);
            wmma::load_matrix_sync(bl[0], Bls + ks * BPADS + wn * 32,      BPADS);
            wmma::load_matrix_sync(bl[1], Bls + ks * BPADS + wn * 32 + 16, BPADS);
#pragma unroll
            for (int im = 0; im < 8; im++) {
                wmma::fragment<wmma::matrix_a, 16, 16, 16, __nv_bfloat16, wmma::row_major> ah;
                wmma::load_matrix_sync(ah, As + (wm * 128 + im * 16) * APADS + ks, APADS);
#pragma unroll
                for (int j = 0; j < 2; j++) {
                    wmma::mma_sync(acc[im][j], ah, bh[j], acc[im][j]);
                    wmma::mma_sync(acc[im][j], ah, bl[j], acc[im][j]);
                }
            }
        }
        if (has) {
            uint4* dA = (uint4*)(Abuf[nxt] + aoff);
            dA[0] = rA0; dA[1] = rA1; dA[2] = rA2; dA[3] = rA3;
            ((uint4*)(Bhb[nxt] + boff))[0] = rB0; ((uint4*)(Bhb[nxt] + boff))[1] = rB1;
            ((uint4*)(Blb[nxt] + boff))[0] = rC0; ((uint4*)(Blb[nxt] + boff))[1] = rC1;
        }
        __syncthreads();
    }

    // epilogue: 4 phases of 64 rows; owner warp row-band wm == ph>>1, im base (ph&1)*4
    for (int ph = 0; ph < 4; ph++) {
        if (wm == (ph >> 1)) {
            int imb = (ph & 1) * 4;
#pragma unroll
            for (int imo = 0; imo < 4; imo++)
#pragma unroll
                for (int j = 0; j < 2; j++)
                    wmma::store_matrix_sync(Cs + (imo * 16) * CPADS + wn * 32 + j * 16,
                                            acc[imb + imo][j], CPADS, wmma::mem_row_major);
        }
        __syncthreads();
        for (int e = tid; e < 64 * 128; e += 256) {
            int rr = e >> 7, cc = e & 127;
            int gr = row0 + ph * 64 + rr, gc = col0 + cc;
            if (gr < M && gc < N) {
                float v = Cs[rr * CPADS + cc];
                if (bias) v += bias[gc];
                size_t ix = (size_t)gr * N + gc;
                if (accum) v += C[ix];
                if (relu) v = fmaxf(v, 0.f);
                C[ix] = v;
            }
        }
        __syncthreads();
    }
}

// ---------------- GRU gating + h = mem_upd + node_features -> bf16 plane ----------------
__global__ void k_gate(const float* __restrict__ mem, const float* __restrict__ nf, int Nn) {
    int idx = blockIdx.x * blockDim.x + threadIdx.x;
    if (idx >= NPAD * KP_S) return;
    int n = idx / KP_S, d = idx - n * KP_S;
    float out = 0.f;
    if (n < Nn && d < MEMD) {
        size_t mi = (size_t)n * MEMD + d;
        float mv = mem[mi];
        float hv;
        if (g_lastpos[n] >= 0) {
            const float* gi = g_GI + (size_t)n * G3;
            const float* gh = g_GH + (size_t)n * G3;
            float r = 1.f / (1.f + expf(-(gi[d] + gh[d])));
            float z = 1.f / (1.f + expf(-(gi[MEMD + d] + gh[MEMD + d])));
            float g = tanhf(gi[2 * MEMD + d] + r * gh[2 * MEMD + d]);
            hv = (1.f - z) * g + z * mv;
        } else {
            hv = mv;
        }
        out = hv + nf[mi];
    }
    g_hh[idx] = __float2bfloat16(out);
}

// ---------------- temporal attention (weight terms pre-GEMMed) ----------------
__global__ void k_attn(const int* __restrict__ nbi, const float* __restrict__ nts,
                       const float* __restrict__ tw, const float* __restrict__ tb,
                       const float* __restrict__ ts, int Nn, int E) {
    int n = blockIdx.x;
    int tid = threadIdx.x;
    if (n >= Nn) {
        __nv_bfloat16 z = __float2bfloat16(0.f);
        for (int d = tid; d < WT_K; d += blockDim.x) g_wtb[(size_t)n * WT_K + d] = z;
        for (int d = tid; d < KP_S; d += blockDim.x) g_aggF[(size_t)n * KP_S + d] = 0.f;
        return;
    }
    __shared__ float s_q[MEMD];
    __shared__ float s_c[2 * TDD];
    __shared__ float s_te[KNB * TDD];
    __shared__ float s_sc[2 * KNB];
    __shared__ float s_at[2 * KNB];
    __shared__ int s_nb[KNB];

    const float* qrow = g_QKV + (size_t)n * NP_Q;
    float t_now = __ldg(&ts[E - 1]);

    if (tid < KNB) s_nb[tid] = nbi[(size_t)n * KNB + tid];
    for (int i = tid; i < MEMD; i += blockDim.x)
        s_q[i] = qrow[i] + g_qconst[i];
    for (int j = tid; j < 2 * TDD; j += blockDim.x)
        s_c[j] = qrow[G3 + j] + g_const2[j];
    for (int j = tid; j < KNB * TDD; j += blockDim.x) {
        int k = j / TDD, t = j - k * TDD;
        float dt = t_now - nts[(size_t)n * KNB + k];
        s_te[j] = cos_acc(dt * tw[t] + tb[t]);
    }
    __syncthreads();

    int wid = tid >> 5, lane = tid & 31;
    for (int p = wid; p < 2 * KNB; p += 4) {
        int k = p >> 1, hh = p & 1;
        const float* kr = g_QKV + (size_t)s_nb[k] * NP_Q + MEMD + hh * DHD;
        const float* qq = s_q + hh * DHD;
        float s = 0.f;
        for (int d = lane; d < DHD; d += 32) s += qq[d] * kr[d];
        const float* cc = s_c + hh * TDD;
        const float* te = s_te + k * TDD;
        for (int t = lane; t < TDD; t += 32) s += cc[t] * te[t];
        for (int o = 16; o; o >>= 1) s += __shfl_down_sync(0xffffffffu, s, o);
        if (lane == 0) s_sc[hh * KNB + k] = s * 0.10783277320343841f;  // 1/sqrt(86)
    }
    __syncthreads();

    if (tid < 2) {
        float mx = -1e30f;
        for (int k = 0; k < KNB; k++) mx = fmaxf(mx, s_sc[tid * KNB + k]);
        float sum = 0.f;
        for (int k = 0; k < KNB; k++) {
            float e = expf(s_sc[tid * KNB + k] - mx);
            s_at[tid * KNB + k] = e;
            sum += e;
        }
        float inv = 1.f / sum;
        for (int k = 0; k < KNB; k++) s_at[tid * KNB + k] *= inv;
    }
    __syncthreads();

    for (int j = tid; j < WT_K; j += blockDim.x) {
        float s = 0.f;
        if (j < 2 * TDD) {
            int hh = j / TDD, t = j - hh * TDD;
            for (int k = 0; k < KNB; k++) s += s_at[hh * KNB + k] * s_te[k * TDD + t];
        }
        g_wtb[(size_t)n * WT_K + j] = __float2bfloat16(s);
    }

    for (int d = tid; d < KP_S; d += blockDim.x) {
        float s = 0.f;
        if (d < MEMD) {
            int hh = d / DHD;
            for (int k = 0; k < KNB; k++)
                s += s_at[hh * KNB + k] * g_QKV[(size_t)s_nb[k] * NP_Q + 2 * MEMD + d];
        }
        g_aggF[(size_t)n * KP_S + d] = s;
    }
}

// ---------------- agg fp32 -> bf16 plane ----------------
__global__ void k_aggsplit(int Nn) {
    int idx = blockIdx.x * blockDim.x + threadIdx.x;
    if (idx >= NPAD * KP_S) return;
    int n = idx / KP_S, d = idx - n * KP_S;
    float v = (n < Nn && d < MEMD) ? g_aggF[idx] : 0.f;
    g_aggh[idx] = __float2bfloat16(v);
}

// ---------------- T1 fp32 -> bf16 plane ----------------
__global__ void k_t1split(int Nn) {
    int idx = blockIdx.x * blockDim.x + threadIdx.x;
    if (idx >= NPAD * KP_S) return;
    int n = idx / KP_S, d = idx - n * KP_S;
    float v = (n < Nn && d < MEMD) ? g_T1[(size_t)n * MEMD + d] : 0.f;
    g_t1h[idx] = __float2bfloat16(v);
}

// ---------------- deterministic final reduction + classifier ----------------
__global__ void k_reduce1(int Nn) {
    int b = blockIdx.x, c = threadIdx.x;
    if (c >= MEMD) return;
    float s = 0.f;
    for (int r = 1 + b; r < Nn; r += RB) s += g_emb[(size_t)r * MEMD + c];
    g_partial[b * MEMD + c] = s;
}

__global__ void k_final(const float* __restrict__ fc2w, const float* __restrict__ fc2b,
                        float* __restrict__ out, int Nn) {
    __shared__ float tm[MEMD];
    int c = threadIdx.x;
    if (c < MEMD) {
        float s = 0.f;
        for (int b = 0; b < RB; b++) s += g_partial[b * MEMD + c];
        tm[c] = tanhf(s / (float)(Nn - 1));
    }
    __syncthreads();
    if (c == 0) {
        float l0 = fc2b[0], l1 = fc2b[1];
        for (int i = 0; i < MEMD; i++) {
            l0 += tm[i] * fc2w[i * 2 + 0];
            l1 += tm[i] * fc2w[i * 2 + 1];
        }
        float mx = fmaxf(l0, l1);
        float e0 = expf(l0 - mx), e1 = expf(l1 - mx);
        float inv = 1.f / (e0 + e1);
        out[0] = e0 * inv;
        out[1] = e1 * inv;
    }
}

// ---------------- host orchestration ----------------
extern "C" void kernel_launch(void* const* d_in, const int* in_sizes, int n_in,
                              void* d_out, int out_size) {
    const float* node_features = (const float*)d_in[0];
    const float* memory        = (const float*)d_in[1];
    const float* last_update   = (const float*)d_in[2];
    const float* timestamps    = (const float*)d_in[3];
    const float* edge_features = (const float*)d_in[4];
    const float* neighbor_ts   = (const float*)d_in[5];
    const float* time_w        = (const float*)d_in[6];
    const float* time_b        = (const float*)d_in[7];
    const float* gru_Wi        = (const float*)d_in[8];
    const float* gru_Wh        = (const float*)d_in[9];
    const float* gru_bi        = (const float*)d_in[10];
    const float* gru_bh        = (const float*)d_in[11];
    const float* Wq            = (const float*)d_in[12];
    const float* Wk            = (const float*)d_in[13];
    const float* Wv            = (const float*)d_in[14];
    const float* W1            = (const float*)d_in[15];
    const float* b1            = (const float*)d_in[16];
    const float* W2            = (const float*)d_in[17];
    const float* b2            = (const float*)d_in[18];
    const float* fc2_w         = (const float*)d_in[19];
    const float* fc2_b         = (const float*)d_in[20];
    const int*   sources       = (const int*)d_in[21];
    const int*   destinations  = (const int*)d_in[22];
    const int*   neighbor_idx  = (const int*)d_in[23];

    int N = in_sizes[0] / FEATD;
    int E = in_sizes[3];
    int MtRows = NPAD / 256;   // 391 row tiles of 256

    static int s_attr_done = 0;
    if (!s_attr_done) {
        cudaFuncSetAttribute(k_gemm2, cudaFuncAttributeMaxDynamicSharedMemorySize, SM_TOT);
        s_attr_done = 1;
    }

    __nv_bfloat16 *pMh, *pMemh, *pHh, *pAh, *pT1h, *pWtb;
    __nv_bfloat16 *pWih, *pWil, *pWhh, *pWhl, *pQh, *pQl, *pBVh, *pBVl;
    __nv_bfloat16 *pW1ah, *pW1al, *pW1bh, *pW1bl, *pW2h, *pW2l;
    float *pGI, *pGH, *pQKV, *pAggF, *pT1, *pEmb;
    cudaGetSymbolAddress((void**)&pMh,   g_Mh);
    cudaGetSymbolAddress((void**)&pMemh, g_memh);
    cudaGetSymbolAddress((void**)&pHh,   g_hh);
    cudaGetSymbolAddress((void**)&pAh,   g_aggh);
    cudaGetSymbolAddress((void**)&pT1h,  g_t1h);
    cudaGetSymbolAddress((void**)&pWtb,  g_wtb);
    cudaGetSymbolAddress((void**)&pWih,  g_BWih);
    cudaGetSymbolAddress((void**)&pWil,  g_BWil);
    cudaGetSymbolAddress((void**)&pWhh,  g_BWhh);
    cudaGetSymbolAddress((void**)&pWhl,  g_BWhl);
    cudaGetSymbolAddress((void**)&pQh,   g_BQh);
    cudaGetSymbolAddress((void**)&pQl,   g_BQl);
    cudaGetSymbolAddress((void**)&pBVh,  g_BVh);
    cudaGetSymbolAddress((void**)&pBVl,  g_BVl);
    cudaGetSymbolAddress((void**)&pW1ah, g_BW1ah);
    cudaGetSymbolAddress((void**)&pW1al, g_BW1al);
    cudaGetSymbolAddress((void**)&pW1bh, g_BW1bh);
    cudaGetSymbolAddress((void**)&pW1bl, g_BW1bl);
    cudaGetSymbolAddress((void**)&pW2h,  g_BW2h);
    cudaGetSymbolAddress((void**)&pW2l,  g_BW2l);
    cudaGetSymbolAddress((void**)&pGI,   g_GI);
    cudaGetSymbolAddress((void**)&pGH,   g_GH);
    cudaGetSymbolAddress((void**)&pQKV,  g_QKV);
    cudaGetSymbolAddress((void**)&pAggF, g_aggF);
    cudaGetSymbolAddress((void**)&pT1,   g_T1);
    cudaGetSymbolAddress((void**)&pEmb,  g_emb);

    // launch order: GI GEMM at my-index 3 (profiled by ncu -s 5)
    k_prep_wi_init<<<(KP_M * NP_G + 255) / 256, 256>>>(gru_Wi, N);
    k_scatter<<<(E + 255) / 256, 256>>>(sources, destinations, E);
    k_build_m<<<NPAD, 128>>>(memory, last_update, timestamps, edge_features,
                             time_w, time_b, sources, destinations, N, E);
    k_gemm2<<<dim3(5, MtRows), 256, SM_TOT>>>(pMh, KP_M, pWih, pWil, NP_G,
                                              gru_bi, pGI, N, G3, KP_M, 0, 0);
    k_memconv<<<(NPAD * KP_S + 255) / 256, 256>>>(memory, N);
    k_prep_wh<<<(KP_S * NP_G + 255) / 256, 256>>>(gru_Wh);
    k_gemm2<<<dim3(5, MtRows), 256, SM_TOT>>>(pMemh, KP_S, pWhh, pWhl, NP_G,
                                              gru_bh, pGH, N, G3, KP_S, 0, 0);
    k_gate<<<(NPAD * KP_S + 255) / 256, 256>>>(memory, node_features, N);

    // extended QKV = h @ [Wq1|Wk1|Wv1|Wc]
    k_prep_qkv<<<(KP_S * NP_Q + 255) / 256, 256>>>(Wq, Wk, Wv);
    k_gemm2<<<dim3(6, MtRows), 256, SM_TOT>>>(pHh, KP_S, pQh, pQl, NP_Q,
                                              nullptr, pQKV, N, NP_Q, KP_S, 0, 0);

    // attention: softmax + gathers; weight terms via GEMM
    k_prep_qconst<<<1, 256>>>(Wq, Wk, time_b);
    k_prep_bv<<<(WT_K * 256 + 255) / 256, 256>>>(Wv);
    k_attn<<<NPAD, 128>>>(neighbor_idx, neighbor_ts, time_w, time_b,
                          timestamps, N, E);
    k_gemm2<<<dim3(2, MtRows), 256, SM_TOT>>>(pWtb, WT_K, pBVh, pBVl, 256,
                                              nullptr, pAggF, NPAD, KP_S, WT_K, 1, 0);
    k_aggsplit<<<(NPAD * KP_S + 255) / 256, 256>>>(N);

    // MLP
    k_prep_w1<<<(KP_S * NP_S + 255) / 256, 256>>>(W1);
    k_prep_w2<<<(KP_S * NP_S + 255) / 256, 256>>>(W2);
    k_gemm2<<<dim3(2, MtRows), 256, SM_TOT>>>(pHh, KP_S, pW1ah, pW1al, NP_S,
                                              b1, pT1, N, MEMD, KP_S, 0, 0);
    k_gemm2<<<dim3(2, MtRows), 256, SM_TOT>>>(pAh, KP_S, pW1bh, pW1bl, NP_S,
                                              nullptr, pT1, N, MEMD, KP_S, 1, 1);
    k_t1split<<<(NPAD * KP_S + 255) / 256, 256>>>(N);
    k_gemm2<<<dim3(2, MtRows), 256, SM_TOT>>>(pT1h, KP_S, pW2h, pW2l, NP_S,
                                              b2, pEmb, N, MEMD, KP_S, 0, 0);

    // classifier head
    k_reduce1<<<RB, 192>>>(N);
    k_final<<<1, 192>>>(fc2_w, fc2_b, (float*)d_out, N);
}

// round 13
// speedup vs baseline: 1.6869x; 1.6869x over previous
#include <cuda_runtime.h>
#include <cuda_bf16.h>
#include <mma.h>
#include <math.h>

using namespace nvcuda;

#define MEMD 172
#define FEATD 172
#define TDD 100
#define KNB 10
#define DHD 86
#define MSGD 616          // 2*MEM + FEAT + TD
#define G3 516            // 3*MEM
#define NMAX 100000
#define NPAD 100096
#define RB 256

// padded K strides for bf16 operand buffers
#define KP_M 640
#define KP_S 192
// padded N strides for B operand buffers
#define NP_G 640
#define NP_Q 768          // 516 + 200 score cols
#define NP_S 256
#define WT_K 256

// ---------------- device scratch ----------------
__device__ int   g_lastpos[NMAX];
__device__ __nv_bfloat16 g_Mh[(size_t)NPAD * KP_M];
__device__ __nv_bfloat16 g_memh[(size_t)NPAD * KP_S];
__device__ __nv_bfloat16 g_hh[(size_t)NPAD * KP_S];
__device__ __nv_bfloat16 g_aggh[(size_t)NPAD * KP_S];
__device__ __nv_bfloat16 g_t1h[(size_t)NPAD * KP_S];
__device__ __nv_bfloat16 g_wtb[(size_t)NPAD * WT_K];
__device__ __nv_bfloat16 g_BWih[KP_M * NP_G];
__device__ __nv_bfloat16 g_BWil[KP_M * NP_G];
__device__ __nv_bfloat16 g_BWhh[KP_S * NP_G];
__device__ __nv_bfloat16 g_BWhl[KP_S * NP_G];
__device__ __nv_bfloat16 g_BQh[KP_S * NP_Q];
__device__ __nv_bfloat16 g_BQl[KP_S * NP_Q];
__device__ __nv_bfloat16 g_BVh[WT_K * 256];
__device__ __nv_bfloat16 g_BVl[WT_K * 256];
__device__ __nv_bfloat16 g_BW1ah[KP_S * NP_S];
__device__ __nv_bfloat16 g_BW1al[KP_S * NP_S];
__device__ __nv_bfloat16 g_BW1bh[KP_S * NP_S];
__device__ __nv_bfloat16 g_BW1bl[KP_S * NP_S];
__device__ __nv_bfloat16 g_BW2h[KP_S * NP_S];
__device__ __nv_bfloat16 g_BW2l[KP_S * NP_S];
__device__ float g_GI[(size_t)NMAX * G3];
__device__ float g_GH[(size_t)NMAX * G3];
__device__ float g_QKV[(size_t)NMAX * NP_Q];
__device__ float g_aggF[(size_t)NPAD * KP_S];
__device__ float g_T1[(size_t)NMAX * MEMD];
__device__ float g_emb[(size_t)NMAX * MEMD];
__device__ float g_qconst[MEMD];
__device__ float g_const2[2 * TDD];
__device__ float g_partial[RB * MEMD];

// fp32 Cody-Waite cos: q = rintf(x/2pi) exact for |q|<2^23; two-term FMA reduction.
__device__ __forceinline__ float cos_acc(float x) {
    float q = rintf(x * 0.15915494f);
    float r = fmaf(-q, 6.2831855f, x);
    r = fmaf(q, 1.7484555e-7f, r);
    return cosf(r);
}

__device__ __forceinline__ void split2(float x, __nv_bfloat16* hi, __nv_bfloat16* lo) {
    __nv_bfloat16 h = __float2bfloat16(x);
    *hi = h;
    *lo = __float2bfloat16(x - __bfloat162float(h));
}

// ---------------- prep kernels ----------------
__global__ void k_prep_wi_init(const float* __restrict__ Wi, int N) {
    int idx = blockIdx.x * blockDim.x + threadIdx.x;
    if (idx < N) g_lastpos[idx] = -1;
    if (idx < KP_M * NP_G) {
        int k = idx / NP_G, n = idx - k * NP_G;
        float v = (k < MSGD && n < G3) ? Wi[n * MSGD + k] : 0.f;
        split2(v, &g_BWih[idx], &g_BWil[idx]);
    }
}

__global__ void k_scatter(const int* __restrict__ src, const int* __restrict__ dst, int E) {
    int e = blockIdx.x * blockDim.x + threadIdx.x;
    if (e < E) {
        atomicMax(&g_lastpos[src[e]], e);
        atomicMax(&g_lastpos[dst[e]], E + e);
    }
}

__global__ void k_prep_wh(const float* __restrict__ Wh) {
    int idx = blockIdx.x * blockDim.x + threadIdx.x;
    if (idx < KP_S * NP_G) {
        int k = idx / NP_G, n = idx - k * NP_G;
        float v = (k < MEMD && n < G3) ? Wh[n * MEMD + k] : 0.f;
        split2(v, &g_BWhh[idx], &g_BWhl[idx]);
    }
}

__global__ void k_prep_qkv(const float* __restrict__ Wq, const float* __restrict__ Wk,
                           const float* __restrict__ Wv) {
    int idx = blockIdx.x * blockDim.x + threadIdx.x;
    if (idx >= KP_S * NP_Q) return;
    int k = idx / NP_Q, n = idx - k * NP_Q;
    float v = 0.f;
    if (k < MEMD) {
        if (n < G3) {
            int sel = n / MEMD, jj = n - sel * MEMD;
            const float* W = (sel == 0) ? Wq : ((sel == 1) ? Wk : Wv);
            v = W[k * MEMD + jj];
        } else if (n < G3 + 2 * TDD) {
            int j = n - G3;
            int hh = j / TDD, t = j - hh * TDD;
            const float* wq = Wq + (size_t)k * MEMD + hh * DHD;
            const float* wk2 = Wk + (size_t)(MEMD + t) * MEMD + hh * DHD;
            float s = 0.f;
            for (int d = 0; d < DHD; d++) s += wq[d] * wk2[d];
            v = s;
        }
    }
    split2(v, &g_BQh[idx], &g_BQl[idx]);
}

__global__ void k_prep_bv(const float* __restrict__ Wv) {
    int idx = blockIdx.x * blockDim.x + threadIdx.x;
    if (idx >= WT_K * 256) return;
    int kk = idx / 256, d = idx - kk * 256;
    float v = 0.f;
    if (kk < 2 * TDD && d < MEMD) {
        int hh = kk / TDD, t = kk - hh * TDD;
        if (d / DHD == hh) v = Wv[(size_t)(MEMD + t) * MEMD + d];
    }
    split2(v, &g_BVh[idx], &g_BVl[idx]);
}

__global__ void k_prep_w1(const float* __restrict__ W1) {
    int idx = blockIdx.x * blockDim.x + threadIdx.x;
    if (idx < KP_S * NP_S) {
        int k = idx / NP_S, n = idx - k * NP_S;
        float va = 0.f, vb = 0.f;
        if (k < MEMD && n < MEMD) {
            va = W1[k * MEMD + n];
            vb = W1[(MEMD + k) * MEMD + n];
        }
        split2(va, &g_BW1ah[idx], &g_BW1al[idx]);
        split2(vb, &g_BW1bh[idx], &g_BW1bl[idx]);
    }
}

__global__ void k_prep_w2(const float* __restrict__ W2) {
    int idx = blockIdx.x * blockDim.x + threadIdx.x;
    if (idx < KP_S * NP_S) {
        int k = idx / NP_S, n = idx - k * NP_S;
        float v = (k < MEMD && n < MEMD) ? W2[k * MEMD + n] : 0.f;
        split2(v, &g_BW2h[idx], &g_BW2l[idx]);
    }
}

__global__ void k_prep_qconst(const float* __restrict__ Wq, const float* __restrict__ Wk,
                              const float* __restrict__ tb) {
    __shared__ float qc[MEMD];
    int j = threadIdx.x;
    if (j < MEMD) {
        float s = 0.f;
        for (int t = 0; t < TDD; t++)
            s += cos_acc(tb[t]) * Wq[(MEMD + t) * MEMD + j];
        qc[j] = s;
        g_qconst[j] = s;
    }
    __syncthreads();
    if (j < 2 * TDD) {
        int hh = j / TDD, t = j - hh * TDD;
        const float* wk2 = Wk + (size_t)(MEMD + t) * MEMD + hh * DHD;
        float s = 0.f;
        for (int d = 0; d < DHD; d++) s += wk2[d] * qc[hh * DHD + d];
        g_const2[j] = s;
    }
}

__global__ void k_memconv(const float* __restrict__ mem, int Nn) {
    int idx = blockIdx.x * blockDim.x + threadIdx.x;
    if (idx >= NPAD * KP_S) return;
    int n = idx / KP_S, d = idx - n * KP_S;
    float v = (n < Nn && d < MEMD) ? mem[(size_t)n * MEMD + d] : 0.f;
    g_memh[idx] = __float2bfloat16(v);
}

// ---------------- build selected message matrix ----------------
__global__ void k_build_m(const float* __restrict__ mem, const float* __restrict__ lu,
                          const float* __restrict__ ts, const float* __restrict__ ef,
                          const float* __restrict__ tw, const float* __restrict__ tb,
                          const int* __restrict__ src, const int* __restrict__ dst,
                          int Nn, int E) {
    int n = blockIdx.x;
    int tid = threadIdx.x;
    __nv_bfloat16* rh = g_Mh + (size_t)n * KP_M;
    __shared__ int s_a, s_b, s_e, s_has;
    __shared__ float s_dt;
    if (tid == 0) {
        int p = (n < Nn) ? g_lastpos[n] : -1;
        if (p < 0) {
            s_has = 0;
        } else {
            s_has = 1;
            int e, a, b;
            if (p < E) { e = p;     a = src[e]; b = dst[e]; }
            else       { e = p - E; a = dst[e]; b = src[e]; }
            s_e = e; s_a = a; s_b = b;
            s_dt = ts[e] - lu[a];
        }
    }
    __syncthreads();
    if (!s_has) {
        __nv_bfloat16 z = __float2bfloat16(0.f);
        for (int i = tid; i < KP_M; i += blockDim.x) rh[i] = z;
        return;
    }
    int a = s_a, b = s_b, e = s_e;
    float dt = s_dt;
    for (int i = tid; i < KP_M; i += blockDim.x) {
        float v = 0.f;
        if (i < MEMD)                  v = mem[(size_t)a * MEMD + i];
        else if (i < 2 * MEMD)         v = mem[(size_t)b * MEMD + (i - MEMD)];
        else if (i < 2 * MEMD + FEATD) v = ef[(size_t)e * FEATD + (i - 2 * MEMD)];
        else if (i < MSGD) { int t = i - (2 * MEMD + FEATD); v = cos_acc(dt * tw[t] + tb[t]); }
        rh[i] = __float2bfloat16(v);
    }
}

// ---------------- 2-product bf16 wmma GEMM: C (+)= Ah @ (Bh + Bl) ------------------------
// Round-11 exact config: 128x128 block, BK=32, 8 warps (2x4), warp tile 64x32,
// double-buffered smem, reg prefetch, 1 sync/iter, __launch_bounds__(256,2).
#define GBK 32
#define APADS 40
#define BPADS 136
#define CPADS 132
#define SM_A0   0
#define SM_A1   10240
#define SM_BH0  20480
#define SM_BL0  29184
#define SM_BH1  37888
#define SM_BL1  46592
#define SM_TOT  55296

__global__ __launch_bounds__(256, 2) void k_gemm2(
        const __nv_bfloat16* __restrict__ Agh, int lda,
        const __nv_bfloat16* __restrict__ Bgh, const __nv_bfloat16* __restrict__ Bgl, int ldb,
        const float* __restrict__ bias, float* __restrict__ C,
        int M, int N, int Kp, int accum, int relu) {
    extern __shared__ __align__(16) unsigned char sraw[];
    __nv_bfloat16* Abuf[2] = { (__nv_bfloat16*)(sraw + SM_A0),  (__nv_bfloat16*)(sraw + SM_A1)  };
    __nv_bfloat16* Bhb[2]  = { (__nv_bfloat16*)(sraw + SM_BH0), (__nv_bfloat16*)(sraw + SM_BH1) };
    __nv_bfloat16* Blb[2]  = { (__nv_bfloat16*)(sraw + SM_BL0), (__nv_bfloat16*)(sraw + SM_BL1) };
    float* Cs = (float*)sraw;

    int tid = threadIdx.x;
    int w = tid >> 5;
    int wm = w >> 2, wn = w & 3;
    int row0 = blockIdx.y * 128;
    int col0 = blockIdx.x * 128;

    wmma::fragment<wmma::accumulator, 16, 16, 16, float> acc[4][2];
#pragma unroll
    for (int i = 0; i < 4; i++)
#pragma unroll
        for (int j = 0; j < 2; j++) wmma::fill_fragment(acc[i][j], 0.f);

    int ar = tid >> 1, akh = (tid & 1) * 16;
    int bk = tid >> 3, bns = (tid & 7) * 16;
    const __nv_bfloat16* pAh = Agh + (size_t)(row0 + ar) * lda + akh;
    const __nv_bfloat16* pBh = Bgh + (size_t)bk * ldb + col0 + bns;
    const __nv_bfloat16* pBl = Bgl + (size_t)bk * ldb + col0 + bns;
    int aoff = ar * APADS + akh;
    int boff = bk * BPADS + bns;

    {
        uint4 a0 = ((const uint4*)pAh)[0], a1 = ((const uint4*)pAh)[1];
        uint4 b0 = ((const uint4*)pBh)[0], b1 = ((const uint4*)pBh)[1];
        uint4 c0 = ((const uint4*)pBl)[0], c1 = ((const uint4*)pBl)[1];
        ((uint4*)(Abuf[0] + aoff))[0] = a0; ((uint4*)(Abuf[0] + aoff))[1] = a1;
        ((uint4*)(Bhb[0]  + boff))[0] = b0; ((uint4*)(Bhb[0]  + boff))[1] = b1;
        ((uint4*)(Blb[0]  + boff))[0] = c0; ((uint4*)(Blb[0]  + boff))[1] = c1;
    }
    __syncthreads();

    int nIter = Kp / GBK;
    for (int it = 0; it < nIter; it++) {
        int cur = it & 1, nxt = cur ^ 1;
        bool has = (it + 1 < nIter);
        uint4 rA0, rA1, rB0, rB1, rC0, rC1;
        if (has) {
            int k1 = (it + 1) * GBK;
            rA0 = ((const uint4*)(pAh + k1))[0];
            rA1 = ((const uint4*)(pAh + k1))[1];
            rB0 = ((const uint4*)(pBh + (size_t)k1 * ldb))[0];
            rB1 = ((const uint4*)(pBh + (size_t)k1 * ldb))[1];
            rC0 = ((const uint4*)(pBl + (size_t)k1 * ldb))[0];
            rC1 = ((const uint4*)(pBl + (size_t)k1 * ldb))[1];
        }
        const __nv_bfloat16* As = Abuf[cur];
        const __nv_bfloat16* Bhs = Bhb[cur];
        const __nv_bfloat16* Bls = Blb[cur];
#pragma unroll
        for (int ks = 0; ks < GBK; ks += 16) {
            wmma::fragment<wmma::matrix_b, 16, 16, 16, __nv_bfloat16, wmma::row_major> bh[2], bl[2];
            wmma::load_matrix_sync(bh[0], Bhs + ks * BPADS + wn * 32,      BPADS);
            wmma::load_matrix_sync(bh[1], Bhs + ks * BPADS + wn * 32 + 16, BPADS);
            wmma::load_matrix_sync(bl[0], Bls + ks * BPADS + wn * 32,      BPADS);
            wmma::load_matrix_sync(bl[1], Bls + ks * BPADS + wn * 32 + 16, BPADS);
#pragma unroll
            for (int im = 0; im < 4; im++) {
                wmma::fragment<wmma::matrix_a, 16, 16, 16, __nv_bfloat16, wmma::row_major> ah;
                wmma::load_matrix_sync(ah, As + (wm * 64 + im * 16) * APADS + ks, APADS);
#pragma unroll
                for (int j = 0; j < 2; j++) {
                    wmma::mma_sync(acc[im][j], ah, bh[j], acc[im][j]);
                    wmma::mma_sync(acc[im][j], ah, bl[j], acc[im][j]);
                }
            }
        }
        if (has) {
            ((uint4*)(Abuf[nxt] + aoff))[0] = rA0; ((uint4*)(Abuf[nxt] + aoff))[1] = rA1;
            ((uint4*)(Bhb[nxt]  + boff))[0] = rB0; ((uint4*)(Bhb[nxt]  + boff))[1] = rB1;
            ((uint4*)(Blb[nxt]  + boff))[0] = rC0; ((uint4*)(Blb[nxt]  + boff))[1] = rC1;
        }
        __syncthreads();
    }

    for (int ph = 0; ph < 2; ph++) {
        if (wm == ph) {
#pragma unroll
            for (int im = 0; im < 4; im++)
#pragma unroll
                for (int j = 0; j < 2; j++)
                    wmma::store_matrix_sync(Cs + (im * 16) * CPADS + wn * 32 + j * 16,
                                            acc[im][j], CPADS, wmma::mem_row_major);
        }
        __syncthreads();
        for (int e = tid; e < 64 * 128; e += 256) {
            int rr = e >> 7, cc = e & 127;
            int gr = row0 + ph * 64 + rr, gc = col0 + cc;
            if (gr < M && gc < N) {
                float v = Cs[rr * CPADS + cc];
                if (bias) v += bias[gc];
                size_t ix = (size_t)gr * N + gc;
                if (accum) v += C[ix];
                if (relu) v = fmaxf(v, 0.f);
                C[ix] = v;
            }
        }
        __syncthreads();
    }
}

// ---------------- GRU gating + h = mem_upd + node_features -> bf16 plane ----------------
__global__ void k_gate(const float* __restrict__ mem, const float* __restrict__ nf, int Nn) {
    int idx = blockIdx.x * blockDim.x + threadIdx.x;
    if (idx >= NPAD * KP_S) return;
    int n = idx / KP_S, d = idx - n * KP_S;
    float out = 0.f;
    if (n < Nn && d < MEMD) {
        size_t mi = (size_t)n * MEMD + d;
        float mv = mem[mi];
        float hv;
        if (g_lastpos[n] >= 0) {
            const float* gi = g_GI + (size_t)n * G3;
            const float* gh = g_GH + (size_t)n * G3;
            float r = 1.f / (1.f + expf(-(gi[d] + gh[d])));
            float z = 1.f / (1.f + expf(-(gi[MEMD + d] + gh[MEMD + d])));
            float g = tanhf(gi[2 * MEMD + d] + r * gh[2 * MEMD + d]);
            hv = (1.f - z) * g + z * mv;
        } else {
            hv = mv;
        }
        out = hv + nf[mi];
    }
    g_hh[idx] = __float2bfloat16(out);
}

// ---------------- temporal attention (weight terms pre-GEMMed) ----------------
__global__ void k_attn(const int* __restrict__ nbi, const float* __restrict__ nts,
                       const float* __restrict__ tw, const float* __restrict__ tb,
                       const float* __restrict__ ts, int Nn, int E) {
    int n = blockIdx.x;
    int tid = threadIdx.x;
    if (n >= Nn) {
        __nv_bfloat16 z = __float2bfloat16(0.f);
        for (int d = tid; d < WT_K; d += blockDim.x) g_wtb[(size_t)n * WT_K + d] = z;
        for (int d = tid; d < KP_S; d += blockDim.x) g_aggF[(size_t)n * KP_S + d] = 0.f;
        return;
    }
    __shared__ float s_q[MEMD];
    __shared__ float s_c[2 * TDD];
    __shared__ float s_te[KNB * TDD];
    __shared__ float s_sc[2 * KNB];
    __shared__ float s_at[2 * KNB];
    __shared__ int s_nb[KNB];

    const float* qrow = g_QKV + (size_t)n * NP_Q;
    float t_now = __ldg(&ts[E - 1]);

    if (tid < KNB) s_nb[tid] = nbi[(size_t)n * KNB + tid];
    for (int i = tid; i < MEMD; i += blockDim.x)
        s_q[i] = qrow[i] + g_qconst[i];
    for (int j = tid; j < 2 * TDD; j += blockDim.x)
        s_c[j] = qrow[G3 + j] + g_const2[j];
    for (int j = tid; j < KNB * TDD; j += blockDim.x) {
        int k = j / TDD, t = j - k * TDD;
        float dt = t_now - nts[(size_t)n * KNB + k];
        s_te[j] = cos_acc(dt * tw[t] + tb[t]);
    }
    __syncthreads();

    int wid = tid >> 5, lane = tid & 31;
    for (int p = wid; p < 2 * KNB; p += 4) {
        int k = p >> 1, hh = p & 1;
        const float* kr = g_QKV + (size_t)s_nb[k] * NP_Q + MEMD + hh * DHD;
        const float* qq = s_q + hh * DHD;
        float s = 0.f;
        for (int d = lane; d < DHD; d += 32) s += qq[d] * kr[d];
        const float* cc = s_c + hh * TDD;
        const float* te = s_te + k * TDD;
        for (int t = lane; t < TDD; t += 32) s += cc[t] * te[t];
        for (int o = 16; o; o >>= 1) s += __shfl_down_sync(0xffffffffu, s, o);
        if (lane == 0) s_sc[hh * KNB + k] = s * 0.10783277320343841f;  // 1/sqrt(86)
    }
    __syncthreads();

    if (tid < 2) {
        float mx = -1e30f;
        for (int k = 0; k < KNB; k++) mx = fmaxf(mx, s_sc[tid * KNB + k]);
        float sum = 0.f;
        for (int k = 0; k < KNB; k++) {
            float e = expf(s_sc[tid * KNB + k] - mx);
            s_at[tid * KNB + k] = e;
            sum += e;
        }
        float inv = 1.f / sum;
        for (int k = 0; k < KNB; k++) s_at[tid * KNB + k] *= inv;
    }
    __syncthreads();

    for (int j = tid; j < WT_K; j += blockDim.x) {
        float s = 0.f;
        if (j < 2 * TDD) {
            int hh = j / TDD, t = j - hh * TDD;
            for (int k = 0; k < KNB; k++) s += s_at[hh * KNB + k] * s_te[k * TDD + t];
        }
        g_wtb[(size_t)n * WT_K + j] = __float2bfloat16(s);
    }

    for (int d = tid; d < KP_S; d += blockDim.x) {
        float s = 0.f;
        if (d < MEMD) {
            int hh = d / DHD;
            for (int k = 0; k < KNB; k++)
                s += s_at[hh * KNB + k] * g_QKV[(size_t)s_nb[k] * NP_Q + 2 * MEMD + d];
        }
        g_aggF[(size_t)n * KP_S + d] = s;
    }
}

// ---------------- agg fp32 -> bf16 plane ----------------
__global__ void k_aggsplit(int Nn) {
    int idx = blockIdx.x * blockDim.x + threadIdx.x;
    if (idx >= NPAD * KP_S) return;
    int n = idx / KP_S, d = idx - n * KP_S;
    float v = (n < Nn && d < MEMD) ? g_aggF[idx] : 0.f;
    g_aggh[idx] = __float2bfloat16(v);
}

// ---------------- T1 fp32 -> bf16 plane ----------------
__global__ void k_t1split(int Nn) {
    int idx = blockIdx.x * blockDim.x + threadIdx.x;
    if (idx >= NPAD * KP_S) return;
    int n = idx / KP_S, d = idx - n * KP_S;
    float v = (n < Nn && d < MEMD) ? g_T1[(size_t)n * MEMD + d] : 0.f;
    g_t1h[idx] = __float2bfloat16(v);
}

// ---------------- deterministic final reduction + classifier ----------------
__global__ void k_reduce1(int Nn) {
    int b = blockIdx.x, c = threadIdx.x;
    if (c >= MEMD) return;
    float s = 0.f;
    for (int r = 1 + b; r < Nn; r += RB) s += g_emb[(size_t)r * MEMD + c];
    g_partial[b * MEMD + c] = s;
}

__global__ void k_final(const float* __restrict__ fc2w, const float* __restrict__ fc2b,
                        float* __restrict__ out, int Nn) {
    __shared__ float tm[MEMD];
    int c = threadIdx.x;
    if (c < MEMD) {
        float s = 0.f;
        for (int b = 0; b < RB; b++) s += g_partial[b * MEMD + c];
        tm[c] = tanhf(s / (float)(Nn - 1));
    }
    __syncthreads();
    if (c == 0) {
        float l0 = fc2b[0], l1 = fc2b[1];
        for (int i = 0; i < MEMD; i++) {
            l0 += tm[i] * fc2w[i * 2 + 0];
            l1 += tm[i] * fc2w[i * 2 + 1];
        }
        float mx = fmaxf(l0, l1);
        float e0 = expf(l0 - mx), e1 = expf(l1 - mx);
        float inv = 1.f / (e0 + e1);
        out[0] = e0 * inv;
        out[1] = e1 * inv;
    }
}

// ---------------- host orchestration ----------------
extern "C" void kernel_launch(void* const* d_in, const int* in_sizes, int n_in,
                              void* d_out, int out_size) {
    const float* node_features = (const float*)d_in[0];
    const float* memory        = (const float*)d_in[1];
    const float* last_update   = (const float*)d_in[2];
    const float* timestamps    = (const float*)d_in[3];
    const float* edge_features = (const float*)d_in[4];
    const float* neighbor_ts   = (const float*)d_in[5];
    const float* time_w        = (const float*)d_in[6];
    const float* time_b        = (const float*)d_in[7];
    const float* gru_Wi        = (const float*)d_in[8];
    const float* gru_Wh        = (const float*)d_in[9];
    const float* gru_bi        = (const float*)d_in[10];
    const float* gru_bh        = (const float*)d_in[11];
    const float* Wq            = (const float*)d_in[12];
    const float* Wk            = (const float*)d_in[13];
    const float* Wv            = (const float*)d_in[14];
    const float* W1            = (const float*)d_in[15];
    const float* b1            = (const float*)d_in[16];
    const float* W2            = (const float*)d_in[17];
    const float* b2            = (const float*)d_in[18];
    const float* fc2_w         = (const float*)d_in[19];
    const float* fc2_b         = (const float*)d_in[20];
    const int*   sources       = (const int*)d_in[21];
    const int*   destinations  = (const int*)d_in[22];
    const int*   neighbor_idx  = (const int*)d_in[23];

    int N = in_sizes[0] / FEATD;
    int E = in_sizes[3];
    int MtRows = NPAD / 128;

    static int s_attr_done = 0;
    if (!s_attr_done) {
        cudaFuncSetAttribute(k_gemm2, cudaFuncAttributeMaxDynamicSharedMemorySize, SM_TOT);
        s_attr_done = 1;
    }

    __nv_bfloat16 *pMh, *pMemh, *pHh, *pAh, *pT1h, *pWtb;
    __nv_bfloat16 *pWih, *pWil, *pWhh, *pWhl, *pQh, *pQl, *pBVh, *pBVl;
    __nv_bfloat16 *pW1ah, *pW1al, *pW1bh, *pW1bl, *pW2h, *pW2l;
    float *pGI, *pGH, *pQKV, *pAggF, *pT1, *pEmb;
    cudaGetSymbolAddress((void**)&pMh,   g_Mh);
    cudaGetSymbolAddress((void**)&pMemh, g_memh);
    cudaGetSymbolAddress((void**)&pHh,   g_hh);
    cudaGetSymbolAddress((void**)&pAh,   g_aggh);
    cudaGetSymbolAddress((void**)&pT1h,  g_t1h);
    cudaGetSymbolAddress((void**)&pWtb,  g_wtb);
    cudaGetSymbolAddress((void**)&pWih,  g_BWih);
    cudaGetSymbolAddress((void**)&pWil,  g_BWil);
    cudaGetSymbolAddress((void**)&pWhh,  g_BWhh);
    cudaGetSymbolAddress((void**)&pWhl,  g_BWhl);
    cudaGetSymbolAddress((void**)&pQh,   g_BQh);
    cudaGetSymbolAddress((void**)&pQl,   g_BQl);
    cudaGetSymbolAddress((void**)&pBVh,  g_BVh);
    cudaGetSymbolAddress((void**)&pBVl,  g_BVl);
    cudaGetSymbolAddress((void**)&pW1ah, g_BW1ah);
    cudaGetSymbolAddress((void**)&pW1al, g_BW1al);
    cudaGetSymbolAddress((void**)&pW1bh, g_BW1bh);
    cudaGetSymbolAddress((void**)&pW1bl, g_BW1bl);
    cudaGetSymbolAddress((void**)&pW2h,  g_BW2h);
    cudaGetSymbolAddress((void**)&pW2l,  g_BW2l);
    cudaGetSymbolAddress((void**)&pGI,   g_GI);
    cudaGetSymbolAddress((void**)&pGH,   g_GH);
    cudaGetSymbolAddress((void**)&pQKV,  g_QKV);
    cudaGetSymbolAddress((void**)&pAggF, g_aggF);
    cudaGetSymbolAddress((void**)&pT1,   g_T1);
    cudaGetSymbolAddress((void**)&pEmb,  g_emb);

    // launch order: GI GEMM at my-index 3 (profiled by ncu -s 5)
    k_prep_wi_init<<<(KP_M * NP_G + 255) / 256, 256>>>(gru_Wi, N);
    k_scatter<<<(E + 255) / 256, 256>>>(sources, destinations, E);
    k_build_m<<<NPAD, 128>>>(memory, last_update, timestamps, edge_features,
                             time_w, time_b, sources, destinations, N, E);
    k_gemm2<<<dim3(5, MtRows), 256, SM_TOT>>>(pMh, KP_M, pWih, pWil, NP_G,
                                              gru_bi, pGI, N, G3, KP_M, 0, 0);
    k_memconv<<<(NPAD * KP_S + 255) / 256, 256>>>(memory, N);
    k_prep_wh<<<(KP_S * NP_G + 255) / 256, 256>>>(gru_Wh);
    k_gemm2<<<dim3(5, MtRows), 256, SM_TOT>>>(pMemh, KP_S, pWhh, pWhl, NP_G,
                                              gru_bh, pGH, N, G3, KP_S, 0, 0);
    k_gate<<<(NPAD * KP_S + 255) / 256, 256>>>(memory, node_features, N);

    // extended QKV = h @ [Wq1|Wk1|Wv1|Wc]
    k_prep_qkv<<<(KP_S * NP_Q + 255) / 256, 256>>>(Wq, Wk, Wv);
    k_gemm2<<<dim3(6, MtRows), 256, SM_TOT>>>(pHh, KP_S, pQh, pQl, NP_Q,
                                              nullptr, pQKV, N, NP_Q, KP_S, 0, 0);

    // attention: softmax + gathers; weight terms via GEMM
    k_prep_qconst<<<1, 256>>>(Wq, Wk, time_b);
    k_prep_bv<<<(WT_K * 256 + 255) / 256, 256>>>(Wv);
    k_attn<<<NPAD, 128>>>(neighbor_idx, neighbor_ts, time_w, time_b,
                          timestamps, N, E);
    k_gemm2<<<dim3(2, MtRows), 256, SM_TOT>>>(pWtb, WT_K, pBVh, pBVl, 256,
                                              nullptr, pAggF, NPAD, KP_S, WT_K, 1, 0);
    k_aggsplit<<<(NPAD * KP_S + 255) / 256, 256>>>(N);

    // MLP
    k_prep_w1<<<(KP_S * NP_S + 255) / 256, 256>>>(W1);
    k_prep_w2<<<(KP_S * NP_S + 255) / 256, 256>>>(W2);
    k_gemm2<<<dim3(2, MtRows), 256, SM_TOT>>>(pHh, KP_S, pW1ah, pW1al, NP_S,
                                              b1, pT1, N, MEMD, KP_S, 0, 0);
    k_gemm2<<<dim3(2, MtRows), 256, SM_TOT>>>(pAh, KP_S, pW1bh, pW1bl, NP_S,
                                              nullptr, pT1, N, MEMD, KP_S, 1, 1);
    k_t1split<<<(NPAD * KP_S + 255) / 256, 256>>>(N);
    k_gemm2<<<dim3(2, MtRows), 256, SM_TOT>>>(pT1h, KP_S, pW2h, pW2l, NP_S,
                                              b2, pEmb, N, MEMD, KP_S, 0, 0);

    // classifier head
    k_reduce1<<<RB, 192>>>(N);
    k_final<<<1, 192>>>(fc2_w, fc2_b, (float*)d_out, N);
}

// round 14
// speedup vs baseline: 1.7435x; 1.0335x over previous
#include <cuda_runtime.h>
#include <cuda_bf16.h>
#include <mma.h>
#include <math.h>

using namespace nvcuda;

#define MEMD 172
#define FEATD 172
#define TDD 100
#define KNB 10
#define DHD 86
#define MSGD 616          // 2*MEM + FEAT + TD
#define G3 516            // 3*MEM
#define NMAX 100000
#define NPAD 100096
#define RB 256

// padded K strides for bf16 operand buffers
#define KP_M 640
#define KP_S 192
// padded N strides for B operand buffers
#define NP_G 640
#define NP_Q 768          // 516 + 200 score cols
#define NP_S 256
#define WT_K 256

// ---------------- device scratch ----------------
__device__ int   g_lastpos[NMAX];
__device__ __nv_bfloat16 g_Mh[(size_t)NPAD * KP_M];
__device__ __nv_bfloat16 g_memh[(size_t)NPAD * KP_S];
__device__ __nv_bfloat16 g_hh[(size_t)NPAD * KP_S];
__device__ __nv_bfloat16 g_aggh[(size_t)NPAD * KP_S];    // written by wt-GEMM bf16 epilogue
__device__ __nv_bfloat16 g_t1h[(size_t)NPAD * KP_S];     // written by W1b bf16 epilogue; pads stay BSS-zero
__device__ __nv_bfloat16 g_wtb[(size_t)NPAD * WT_K];
__device__ __nv_bfloat16 g_QKVb[(size_t)NPAD * NP_Q];    // bf16 QKV+score-c (gather-friendly)
__device__ __nv_bfloat16 g_BWih[KP_M * NP_G];
__device__ __nv_bfloat16 g_BWil[KP_M * NP_G];
__device__ __nv_bfloat16 g_BWhh[KP_S * NP_G];
__device__ __nv_bfloat16 g_BWhl[KP_S * NP_G];
__device__ __nv_bfloat16 g_BQh[KP_S * NP_Q];
__device__ __nv_bfloat16 g_BQl[KP_S * NP_Q];
__device__ __nv_bfloat16 g_BVh[WT_K * 256];
__device__ __nv_bfloat16 g_BVl[WT_K * 256];
__device__ __nv_bfloat16 g_BW1ah[KP_S * NP_S];
__device__ __nv_bfloat16 g_BW1al[KP_S * NP_S];
__device__ __nv_bfloat16 g_BW1bh[KP_S * NP_S];
__device__ __nv_bfloat16 g_BW1bl[KP_S * NP_S];
__device__ __nv_bfloat16 g_BW2h[KP_S * NP_S];
__device__ __nv_bfloat16 g_BW2l[KP_S * NP_S];
__device__ float g_GI[(size_t)NMAX * G3];
__device__ float g_GH[(size_t)NMAX * G3];
__device__ float g_aggF[(size_t)NPAD * KP_S];
__device__ float g_T1[(size_t)NMAX * MEMD];
__device__ float g_emb[(size_t)NMAX * MEMD];
__device__ float g_qconst[MEMD];
__device__ float g_const2[2 * TDD];
__device__ float g_partial[RB * MEMD];

// fp32 Cody-Waite cos: q = rintf(x/2pi) exact for |q|<2^23; two-term FMA reduction.
__device__ __forceinline__ float cos_acc(float x) {
    float q = rintf(x * 0.15915494f);
    float r = fmaf(-q, 6.2831855f, x);
    r = fmaf(q, 1.7484555e-7f, r);
    return cosf(r);
}

__device__ __forceinline__ void split2(float x, __nv_bfloat16* hi, __nv_bfloat16* lo) {
    __nv_bfloat16 h = __float2bfloat16(x);
    *hi = h;
    *lo = __float2bfloat16(x - __bfloat162float(h));
}

// ---------------- prep kernels ----------------
__global__ void k_prep_wi_init(const float* __restrict__ Wi, int N) {
    int idx = blockIdx.x * blockDim.x + threadIdx.x;
    if (idx < N) g_lastpos[idx] = -1;
    if (idx < KP_M * NP_G) {
        int k = idx / NP_G, n = idx - k * NP_G;
        float v = (k < MSGD && n < G3) ? Wi[n * MSGD + k] : 0.f;
        split2(v, &g_BWih[idx], &g_BWil[idx]);
    }
}

__global__ void k_scatter(const int* __restrict__ src, const int* __restrict__ dst, int E) {
    int e = blockIdx.x * blockDim.x + threadIdx.x;
    if (e < E) {
        atomicMax(&g_lastpos[src[e]], e);
        atomicMax(&g_lastpos[dst[e]], E + e);
    }
}

__global__ void k_prep_wh(const float* __restrict__ Wh) {
    int idx = blockIdx.x * blockDim.x + threadIdx.x;
    if (idx < KP_S * NP_G) {
        int k = idx / NP_G, n = idx - k * NP_G;
        float v = (k < MEMD && n < G3) ? Wh[n * MEMD + k] : 0.f;
        split2(v, &g_BWhh[idx], &g_BWhl[idx]);
    }
}

__global__ void k_prep_qkv(const float* __restrict__ Wq, const float* __restrict__ Wk,
                           const float* __restrict__ Wv) {
    int idx = blockIdx.x * blockDim.x + threadIdx.x;
    if (idx >= KP_S * NP_Q) return;
    int k = idx / NP_Q, n = idx - k * NP_Q;
    float v = 0.f;
    if (k < MEMD) {
        if (n < G3) {
            int sel = n / MEMD, jj = n - sel * MEMD;
            const float* W = (sel == 0) ? Wq : ((sel == 1) ? Wk : Wv);
            v = W[k * MEMD + jj];
        } else if (n < G3 + 2 * TDD) {
            int j = n - G3;
            int hh = j / TDD, t = j - hh * TDD;
            const float* wq = Wq + (size_t)k * MEMD + hh * DHD;
            const float* wk2 = Wk + (size_t)(MEMD + t) * MEMD + hh * DHD;
            float s = 0.f;
            for (int d = 0; d < DHD; d++) s += wq[d] * wk2[d];
            v = s;
        }
    }
    split2(v, &g_BQh[idx], &g_BQl[idx]);
}

__global__ void k_prep_bv(const float* __restrict__ Wv) {
    int idx = blockIdx.x * blockDim.x + threadIdx.x;
    if (idx >= WT_K * 256) return;
    int kk = idx / 256, d = idx - kk * 256;
    float v = 0.f;
    if (kk < 2 * TDD && d < MEMD) {
        int hh = kk / TDD, t = kk - hh * TDD;
        if (d / DHD == hh) v = Wv[(size_t)(MEMD + t) * MEMD + d];
    }
    split2(v, &g_BVh[idx], &g_BVl[idx]);
}

__global__ void k_prep_w1(const float* __restrict__ W1) {
    int idx = blockIdx.x * blockDim.x + threadIdx.x;
    if (idx < KP_S * NP_S) {
        int k = idx / NP_S, n = idx - k * NP_S;
        float va = 0.f, vb = 0.f;
        if (k < MEMD && n < MEMD) {
            va = W1[k * MEMD + n];
            vb = W1[(MEMD + k) * MEMD + n];
        }
        split2(va, &g_BW1ah[idx], &g_BW1al[idx]);
        split2(vb, &g_BW1bh[idx], &g_BW1bl[idx]);
    }
}

__global__ void k_prep_w2(const float* __restrict__ W2) {
    int idx = blockIdx.x * blockDim.x + threadIdx.x;
    if (idx < KP_S * NP_S) {
        int k = idx / NP_S, n = idx - k * NP_S;
        float v = (k < MEMD && n < MEMD) ? W2[k * MEMD + n] : 0.f;
        split2(v, &g_BW2h[idx], &g_BW2l[idx]);
    }
}

__global__ void k_prep_qconst(const float* __restrict__ Wq, const float* __restrict__ Wk,
                              const float* __restrict__ tb) {
    __shared__ float qc[MEMD];
    int j = threadIdx.x;
    if (j < MEMD) {
        float s = 0.f;
        for (int t = 0; t < TDD; t++)
            s += cos_acc(tb[t]) * Wq[(MEMD + t) * MEMD + j];
        qc[j] = s;
        g_qconst[j] = s;
    }
    __syncthreads();
    if (j < 2 * TDD) {
        int hh = j / TDD, t = j - hh * TDD;
        const float* wk2 = Wk + (size_t)(MEMD + t) * MEMD + hh * DHD;
        float s = 0.f;
        for (int d = 0; d < DHD; d++) s += wk2[d] * qc[hh * DHD + d];
        g_const2[j] = s;
    }
}

__global__ void k_memconv(const float* __restrict__ mem, int Nn) {
    int idx = blockIdx.x * blockDim.x + threadIdx.x;
    if (idx >= NPAD * KP_S) return;
    int n = idx / KP_S, d = idx - n * KP_S;
    float v = (n < Nn && d < MEMD) ? mem[(size_t)n * MEMD + d] : 0.f;
    g_memh[idx] = __float2bfloat16(v);
}

// ---------------- build selected message matrix ----------------
__global__ void k_build_m(const float* __restrict__ mem, const float* __restrict__ lu,
                          const float* __restrict__ ts, const float* __restrict__ ef,
                          const float* __restrict__ tw, const float* __restrict__ tb,
                          const int* __restrict__ src, const int* __restrict__ dst,
                          int Nn, int E) {
    int n = blockIdx.x;
    int tid = threadIdx.x;
    __nv_bfloat16* rh = g_Mh + (size_t)n * KP_M;
    __shared__ int s_a, s_b, s_e, s_has;
    __shared__ float s_dt;
    if (tid == 0) {
        int p = (n < Nn) ? g_lastpos[n] : -1;
        if (p < 0) {
            s_has = 0;
        } else {
            s_has = 1;
            int e, a, b;
            if (p < E) { e = p;     a = src[e]; b = dst[e]; }
            else       { e = p - E; a = dst[e]; b = src[e]; }
            s_e = e; s_a = a; s_b = b;
            s_dt = ts[e] - lu[a];
        }
    }
    __syncthreads();
    if (!s_has) {
        __nv_bfloat16 z = __float2bfloat16(0.f);
        for (int i = tid; i < KP_M; i += blockDim.x) rh[i] = z;
        return;
    }
    int a = s_a, b = s_b, e = s_e;
    float dt = s_dt;
    for (int i = tid; i < KP_M; i += blockDim.x) {
        float v = 0.f;
        if (i < MEMD)                  v = mem[(size_t)a * MEMD + i];
        else if (i < 2 * MEMD)         v = mem[(size_t)b * MEMD + (i - MEMD)];
        else if (i < 2 * MEMD + FEATD) v = ef[(size_t)e * FEATD + (i - 2 * MEMD)];
        else if (i < MSGD) { int t = i - (2 * MEMD + FEATD); v = cos_acc(dt * tw[t] + tb[t]); }
        rh[i] = __float2bfloat16(v);
    }
}

// ---------------- 2-product bf16 wmma GEMM: C (+)= Ah @ (Bh + Bl) ------------------------
// Round-11 config; epilogue optionally writes bf16 Cb[ldcb] instead of fp32 C[N].
// accum always reads fp32 C[N] (may differ from output target).
#define GBK 32
#define APADS 40
#define BPADS 136
#define CPADS 132
#define SM_A0   0
#define SM_A1   10240
#define SM_BH0  20480
#define SM_BL0  29184
#define SM_BH1  37888
#define SM_BL1  46592
#define SM_TOT  55296

__global__ __launch_bounds__(256, 2) void k_gemm2(
        const __nv_bfloat16* __restrict__ Agh, int lda,
        const __nv_bfloat16* __restrict__ Bgh, const __nv_bfloat16* __restrict__ Bgl, int ldb,
        const float* __restrict__ bias, float* __restrict__ C,
        __nv_bfloat16* __restrict__ Cb, int ldcb,
        int M, int N, int Kp, int accum, int relu) {
    extern __shared__ __align__(16) unsigned char sraw[];
    __nv_bfloat16* Abuf[2] = { (__nv_bfloat16*)(sraw + SM_A0),  (__nv_bfloat16*)(sraw + SM_A1)  };
    __nv_bfloat16* Bhb[2]  = { (__nv_bfloat16*)(sraw + SM_BH0), (__nv_bfloat16*)(sraw + SM_BH1) };
    __nv_bfloat16* Blb[2]  = { (__nv_bfloat16*)(sraw + SM_BL0), (__nv_bfloat16*)(sraw + SM_BL1) };
    float* Cs = (float*)sraw;

    int tid = threadIdx.x;
    int w = tid >> 5;
    int wm = w >> 2, wn = w & 3;
    int row0 = blockIdx.y * 128;
    int col0 = blockIdx.x * 128;

    wmma::fragment<wmma::accumulator, 16, 16, 16, float> acc[4][2];
#pragma unroll
    for (int i = 0; i < 4; i++)
#pragma unroll
        for (int j = 0; j < 2; j++) wmma::fill_fragment(acc[i][j], 0.f);

    int ar = tid >> 1, akh = (tid & 1) * 16;
    int bk = tid >> 3, bns = (tid & 7) * 16;
    const __nv_bfloat16* pAh = Agh + (size_t)(row0 + ar) * lda + akh;
    const __nv_bfloat16* pBh = Bgh + (size_t)bk * ldb + col0 + bns;
    const __nv_bfloat16* pBl = Bgl + (size_t)bk * ldb + col0 + bns;
    int aoff = ar * APADS + akh;
    int boff = bk * BPADS + bns;

    {
        uint4 a0 = ((const uint4*)pAh)[0], a1 = ((const uint4*)pAh)[1];
        uint4 b0 = ((const uint4*)pBh)[0], b1 = ((const uint4*)pBh)[1];
        uint4 c0 = ((const uint4*)pBl)[0], c1 = ((const uint4*)pBl)[1];
        ((uint4*)(Abuf[0] + aoff))[0] = a0; ((uint4*)(Abuf[0] + aoff))[1] = a1;
        ((uint4*)(Bhb[0]  + boff))[0] = b0; ((uint4*)(Bhb[0]  + boff))[1] = b1;
        ((uint4*)(Blb[0]  + boff))[0] = c0; ((uint4*)(Blb[0]  + boff))[1] = c1;
    }
    __syncthreads();

    int nIter = Kp / GBK;
    for (int it = 0; it < nIter; it++) {
        int cur = it & 1, nxt = cur ^ 1;
        bool has = (it + 1 < nIter);
        uint4 rA0, rA1, rB0, rB1, rC0, rC1;
        if (has) {
            int k1 = (it + 1) * GBK;
            rA0 = ((const uint4*)(pAh + k1))[0];
            rA1 = ((const uint4*)(pAh + k1))[1];
            rB0 = ((const uint4*)(pBh + (size_t)k1 * ldb))[0];
            rB1 = ((const uint4*)(pBh + (size_t)k1 * ldb))[1];
            rC0 = ((const uint4*)(pBl + (size_t)k1 * ldb))[0];
            rC1 = ((const uint4*)(pBl + (size_t)k1 * ldb))[1];
        }
        const __nv_bfloat16* As = Abuf[cur];
        const __nv_bfloat16* Bhs = Bhb[cur];
        const __nv_bfloat16* Bls = Blb[cur];
#pragma unroll
        for (int ks = 0; ks < GBK; ks += 16) {
            wmma::fragment<wmma::matrix_b, 16, 16, 16, __nv_bfloat16, wmma::row_major> bh[2], bl[2];
            wmma::load_matrix_sync(bh[0], Bhs + ks * BPADS + wn * 32,      BPADS);
            wmma::load_matrix_sync(bh[1], Bhs + ks * BPADS + wn * 32 + 16, BPADS);
            wmma::load_matrix_sync(bl[0], Bls + ks * BPADS + wn * 32,      BPADS);
            wmma::load_matrix_sync(bl[1], Bls + ks * BPADS + wn * 32 + 16, BPADS);
#pragma unroll
            for (int im = 0; im < 4; im++) {
                wmma::fragment<wmma::matrix_a, 16, 16, 16, __nv_bfloat16, wmma::row_major> ah;
                wmma::load_matrix_sync(ah, As + (wm * 64 + im * 16) * APADS + ks, APADS);
#pragma unroll
                for (int j = 0; j < 2; j++) {
                    wmma::mma_sync(acc[im][j], ah, bh[j], acc[im][j]);
                    wmma::mma_sync(acc[im][j], ah, bl[j], acc[im][j]);
                }
            }
        }
        if (has) {
            ((uint4*)(Abuf[nxt] + aoff))[0] = rA0; ((uint4*)(Abuf[nxt] + aoff))[1] = rA1;
            ((uint4*)(Bhb[nxt]  + boff))[0] = rB0; ((uint4*)(Bhb[nxt]  + boff))[1] = rB1;
            ((uint4*)(Blb[nxt]  + boff))[0] = rC0; ((uint4*)(Blb[nxt]  + boff))[1] = rC1;
        }
        __syncthreads();
    }

    for (int ph = 0; ph < 2; ph++) {
        if (wm == ph) {
#pragma unroll
            for (int im = 0; im < 4; im++)
#pragma unroll
                for (int j = 0; j < 2; j++)
                    wmma::store_matrix_sync(Cs + (im * 16) * CPADS + wn * 32 + j * 16,
                                            acc[im][j], CPADS, wmma::mem_row_major);
        }
        __syncthreads();
        for (int e = tid; e < 64 * 128; e += 256) {
            int rr = e >> 7, cc = e & 127;
            int gr = row0 + ph * 64 + rr, gc = col0 + cc;
            if (gr < M && gc < N) {
                float v = Cs[rr * CPADS + cc];
                if (bias) v += bias[gc];
                if (accum) v += C[(size_t)gr * N + gc];
                if (relu) v = fmaxf(v, 0.f);
                if (Cb) Cb[(size_t)gr * ldcb + gc] = __float2bfloat16(v);
                else    C[(size_t)gr * N + gc] = v;
            }
        }
        __syncthreads();
    }
}

// ---------------- GRU gating + h = mem_upd + node_features -> bf16 plane ----------------
__global__ void k_gate(const float* __restrict__ mem, const float* __restrict__ nf, int Nn) {
    int idx = blockIdx.x * blockDim.x + threadIdx.x;
    if (idx >= NPAD * KP_S) return;
    int n = idx / KP_S, d = idx - n * KP_S;
    float out = 0.f;
    if (n < Nn && d < MEMD) {
        size_t mi = (size_t)n * MEMD + d;
        float mv = mem[mi];
        float hv;
        if (g_lastpos[n] >= 0) {
            const float* gi = g_GI + (size_t)n * G3;
            const float* gh = g_GH + (size_t)n * G3;
            float r = 1.f / (1.f + expf(-(gi[d] + gh[d])));
            float z = 1.f / (1.f + expf(-(gi[MEMD + d] + gh[MEMD + d])));
            float g = tanhf(gi[2 * MEMD + d] + r * gh[2 * MEMD + d]);
            hv = (1.f - z) * g + z * mv;
        } else {
            hv = mv;
        }
        out = hv + nf[mi];
    }
    g_hh[idx] = __float2bfloat16(out);
}

// ---------------- temporal attention (bf16 QKV gathers) ----------------
__global__ void k_attn(const int* __restrict__ nbi, const float* __restrict__ nts,
                       const float* __restrict__ tw, const float* __restrict__ tb,
                       const float* __restrict__ ts, int Nn, int E) {
    int n = blockIdx.x;
    int tid = threadIdx.x;
    if (n >= Nn) {
        __nv_bfloat16 z = __float2bfloat16(0.f);
        for (int d = tid; d < WT_K; d += blockDim.x) g_wtb[(size_t)n * WT_K + d] = z;
        for (int d = tid; d < KP_S; d += blockDim.x) g_aggF[(size_t)n * KP_S + d] = 0.f;
        return;
    }
    __shared__ float s_q[MEMD];
    __shared__ float s_c[2 * TDD];
    __shared__ float s_te[KNB * TDD];
    __shared__ float s_sc[2 * KNB];
    __shared__ float s_at[2 * KNB];
    __shared__ int s_nb[KNB];

    const __nv_bfloat16* qrow = g_QKVb + (size_t)n * NP_Q;
    float t_now = __ldg(&ts[E - 1]);

    if (tid < KNB) s_nb[tid] = nbi[(size_t)n * KNB + tid];
    for (int i = tid; i < MEMD; i += blockDim.x)
        s_q[i] = __bfloat162float(qrow[i]) + g_qconst[i];
    for (int j = tid; j < 2 * TDD; j += blockDim.x)
        s_c[j] = __bfloat162float(qrow[G3 + j]) + g_const2[j];
    for (int j = tid; j < KNB * TDD; j += blockDim.x) {
        int k = j / TDD, t = j - k * TDD;
        float dt = t_now - nts[(size_t)n * KNB + k];
        s_te[j] = cos_acc(dt * tw[t] + tb[t]);
    }
    __syncthreads();

    int wid = tid >> 5, lane = tid & 31;
    for (int p = wid; p < 2 * KNB; p += 4) {
        int k = p >> 1, hh = p & 1;
        const __nv_bfloat16* kr = g_QKVb + (size_t)s_nb[k] * NP_Q + MEMD + hh * DHD;
        const float* qq = s_q + hh * DHD;
        float s = 0.f;
        for (int d = lane; d < DHD; d += 32) s += qq[d] * __bfloat162float(kr[d]);
        const float* cc = s_c + hh * TDD;
        const float* te = s_te + k * TDD;
        for (int t = lane; t < TDD; t += 32) s += cc[t] * te[t];
        for (int o = 16; o; o >>= 1) s += __shfl_down_sync(0xffffffffu, s, o);
        if (lane == 0) s_sc[hh * KNB + k] = s * 0.10783277320343841f;  // 1/sqrt(86)
    }
    __syncthreads();

    if (tid < 2) {
        float mx = -1e30f;
        for (int k = 0; k < KNB; k++) mx = fmaxf(mx, s_sc[tid * KNB + k]);
        float sum = 0.f;
        for (int k = 0; k < KNB; k++) {
            float e = expf(s_sc[tid * KNB + k] - mx);
            s_at[tid * KNB + k] = e;
            sum += e;
        }
        float inv = 1.f / sum;
        for (int k = 0; k < KNB; k++) s_at[tid * KNB + k] *= inv;
    }
    __syncthreads();

    for (int j = tid; j < WT_K; j += blockDim.x) {
        float s = 0.f;
        if (j < 2 * TDD) {
            int hh = j / TDD, t = j - hh * TDD;
            for (int k = 0; k < KNB; k++) s += s_at[hh * KNB + k] * s_te[k * TDD + t];
        }
        g_wtb[(size_t)n * WT_K + j] = __float2bfloat16(s);
    }

    for (int d = tid; d < KP_S; d += blockDim.x) {
        float s = 0.f;
        if (d < MEMD) {
            int hh = d / DHD;
            for (int k = 0; k < KNB; k++)
                s += s_at[hh * KNB + k] *
                     __bfloat162float(g_QKVb[(size_t)s_nb[k] * NP_Q + 2 * MEMD + d]);
        }
        g_aggF[(size_t)n * KP_S + d] = s;
    }
}

// ---------------- deterministic final reduction + classifier ----------------
__global__ void k_reduce1(int Nn) {
    int b = blockIdx.x, c = threadIdx.x;
    if (c >= MEMD) return;
    float s = 0.f;
    for (int r = 1 + b; r < Nn; r += RB) s += g_emb[(size_t)r * MEMD + c];
    g_partial[b * MEMD + c] = s;
}

__global__ void k_final(const float* __restrict__ fc2w, const float* __restrict__ fc2b,
                        float* __restrict__ out, int Nn) {
    __shared__ float tm[MEMD];
    int c = threadIdx.x;
    if (c < MEMD) {
        float s = 0.f;
        for (int b = 0; b < RB; b++) s += g_partial[b * MEMD + c];
        tm[c] = tanhf(s / (float)(Nn - 1));
    }
    __syncthreads();
    if (c == 0) {
        float l0 = fc2b[0], l1 = fc2b[1];
        for (int i = 0; i < MEMD; i++) {
            l0 += tm[i] * fc2w[i * 2 + 0];
            l1 += tm[i] * fc2w[i * 2 + 1];
        }
        float mx = fmaxf(l0, l1);
        float e0 = expf(l0 - mx), e1 = expf(l1 - mx);
        float inv = 1.f / (e0 + e1);
        out[0] = e0 * inv;
        out[1] = e1 * inv;
    }
}

// ---------------- host orchestration ----------------
extern "C" void kernel_launch(void* const* d_in, const int* in_sizes, int n_in,
                              void* d_out, int out_size) {
    const float* node_features = (const float*)d_in[0];
    const float* memory        = (const float*)d_in[1];
    const float* last_update   = (const float*)d_in[2];
    const float* timestamps    = (const float*)d_in[3];
    const float* edge_features = (const float*)d_in[4];
    const float* neighbor_ts   = (const float*)d_in[5];
    const float* time_w        = (const float*)d_in[6];
    const float* time_b        = (const float*)d_in[7];
    const float* gru_Wi        = (const float*)d_in[8];
    const float* gru_Wh        = (const float*)d_in[9];
    const float* gru_bi        = (const float*)d_in[10];
    const float* gru_bh        = (const float*)d_in[11];
    const float* Wq            = (const float*)d_in[12];
    const float* Wk            = (const float*)d_in[13];
    const float* Wv            = (const float*)d_in[14];
    const float* W1            = (const float*)d_in[15];
    const float* b1            = (const float*)d_in[16];
    const float* W2            = (const float*)d_in[17];
    const float* b2            = (const float*)d_in[18];
    const float* fc2_w         = (const float*)d_in[19];
    const float* fc2_b         = (const float*)d_in[20];
    const int*   sources       = (const int*)d_in[21];
    const int*   destinations  = (const int*)d_in[22];
    const int*   neighbor_idx  = (const int*)d_in[23];

    int N = in_sizes[0] / FEATD;
    int E = in_sizes[3];
    int MtRows = NPAD / 128;

    static int s_attr_done = 0;
    if (!s_attr_done) {
        cudaFuncSetAttribute(k_gemm2, cudaFuncAttributeMaxDynamicSharedMemorySize, SM_TOT);
        s_attr_done = 1;
    }

    __nv_bfloat16 *pMh, *pMemh, *pHh, *pAh, *pT1h, *pWtb, *pQKVb;
    __nv_bfloat16 *pWih, *pWil, *pWhh, *pWhl, *pQh, *pQl, *pBVh, *pBVl;
    __nv_bfloat16 *pW1ah, *pW1al, *pW1bh, *pW1bl, *pW2h, *pW2l;
    float *pGI, *pGH, *pAggF, *pT1, *pEmb;
    cudaGetSymbolAddress((void**)&pMh,   g_Mh);
    cudaGetSymbolAddress((void**)&pMemh, g_memh);
    cudaGetSymbolAddress((void**)&pHh,   g_hh);
    cudaGetSymbolAddress((void**)&pAh,   g_aggh);
    cudaGetSymbolAddress((void**)&pT1h,  g_t1h);
    cudaGetSymbolAddress((void**)&pWtb,  g_wtb);
    cudaGetSymbolAddress((void**)&pQKVb, g_QKVb);
    cudaGetSymbolAddress((void**)&pWih,  g_BWih);
    cudaGetSymbolAddress((void**)&pWil,  g_BWil);
    cudaGetSymbolAddress((void**)&pWhh,  g_BWhh);
    cudaGetSymbolAddress((void**)&pWhl,  g_BWhl);
    cudaGetSymbolAddress((void**)&pQh,   g_BQh);
    cudaGetSymbolAddress((void**)&pQl,   g_BQl);
    cudaGetSymbolAddress((void**)&pBVh,  g_BVh);
    cudaGetSymbolAddress((void**)&pBVl,  g_BVl);
    cudaGetSymbolAddress((void**)&pW1ah, g_BW1ah);
    cudaGetSymbolAddress((void**)&pW1al, g_BW1al);
    cudaGetSymbolAddress((void**)&pW1bh, g_BW1bh);
    cudaGetSymbolAddress((void**)&pW1bl, g_BW1bl);
    cudaGetSymbolAddress((void**)&pW2h,  g_BW2h);
    cudaGetSymbolAddress((void**)&pW2l,  g_BW2l);
    cudaGetSymbolAddress((void**)&pGI,   g_GI);
    cudaGetSymbolAddress((void**)&pGH,   g_GH);
    cudaGetSymbolAddress((void**)&pAggF, g_aggF);
    cudaGetSymbolAddress((void**)&pT1,   g_T1);
    cudaGetSymbolAddress((void**)&pEmb,  g_emb);

    k_prep_wi_init<<<(KP_M * NP_G + 255) / 256, 256>>>(gru_Wi, N);
    k_scatter<<<(E + 255) / 256, 256>>>(sources, destinations, E);
    k_build_m<<<NPAD, 128>>>(memory, last_update, timestamps, edge_features,
                             time_w, time_b, sources, destinations, N, E);
    k_gemm2<<<dim3(5, MtRows), 256, SM_TOT>>>(pMh, KP_M, pWih, pWil, NP_G,
                                              gru_bi, pGI, nullptr, 0, N, G3, KP_M, 0, 0);
    k_memconv<<<(NPAD * KP_S + 255) / 256, 256>>>(memory, N);
    k_prep_wh<<<(KP_S * NP_G + 255) / 256, 256>>>(gru_Wh);
    k_gemm2<<<dim3(5, MtRows), 256, SM_TOT>>>(pMemh, KP_S, pWhh, pWhl, NP_G,
                                              gru_bh, pGH, nullptr, 0, N, G3, KP_S, 0, 0);
    k_gate<<<(NPAD * KP_S + 255) / 256, 256>>>(memory, node_features, N);

    // extended QKV = h @ [Wq1|Wk1|Wv1|Wc] -> bf16 (gather-friendly)
    k_prep_qkv<<<(KP_S * NP_Q + 255) / 256, 256>>>(Wq, Wk, Wv);
    k_gemm2<<<dim3(6, MtRows), 256, SM_TOT>>>(pHh, KP_S, pQh, pQl, NP_Q,
                                              nullptr, nullptr, pQKVb, NP_Q,
                                              N, NP_Q, KP_S, 0, 0);

    // attention: softmax + bf16 gathers; weight terms via GEMM
    k_prep_qconst<<<1, 256>>>(Wq, Wk, time_b);
    k_prep_bv<<<(WT_K * 256 + 255) / 256, 256>>>(Wv);
    k_attn<<<NPAD, 128>>>(neighbor_idx, neighbor_ts, time_w, time_b,
                          timestamps, N, E);
    // agg = (neighbor part in aggF) + wt @ Wv2blk -> bf16 aggh directly
    k_gemm2<<<dim3(2, MtRows), 256, SM_TOT>>>(pWtb, WT_K, pBVh, pBVl, 256,
                                              nullptr, pAggF, pAh, KP_S,
                                              NPAD, KP_S, WT_K, 1, 0);

    // MLP: T1f = h@W1a + b1 ; t1h = bf16(relu(T1f + agg@W1b)) ; emb = T1@W2 + b2
    k_prep_w1<<<(KP_S * NP_S + 255) / 256, 256>>>(W1);
    k_prep_w2<<<(KP_S * NP_S + 255) / 256, 256>>>(W2);
    k_gemm2<<<dim3(2, MtRows), 256, SM_TOT>>>(pHh, KP_S, pW1ah, pW1al, NP_S,
                                              b1, pT1, nullptr, 0, N, MEMD, KP_S, 0, 0);
    k_gemm2<<<dim3(2, MtRows), 256, SM_TOT>>>(pAh, KP_S, pW1bh, pW1bl, NP_S,
                                              nullptr, pT1, pT1h, KP_S,
                                              N, MEMD, KP_S, 1, 1);
    k_gemm2<<<dim3(2, MtRows), 256, SM_TOT>>>(pT1h, KP_S, pW2h, pW2l, NP_S,
                                              b2, pEmb, nullptr, 0, N, MEMD, KP_S, 0, 0);

    // classifier head
    k_reduce1<<<RB, 192>>>(N);
    k_final<<<1, 192>>>(fc2_w, fc2_b, (float*)d_out, N);
}

// round 15
// speedup vs baseline: 1.8736x; 1.0746x over previous
#include <cuda_runtime.h>
#include <cuda_bf16.h>
#include <mma.h>
#include <math.h>

using namespace nvcuda;

#define MEMD 172
#define FEATD 172
#define TDD 100
#define KNB 10
#define DHD 86
#define MSGD 616          // 2*MEM + FEAT + TD
#define G3 516            // 3*MEM
#define NMAX 100000
#define NPAD 100096
#define RB 256

// padded strides
#define KP_M 640
#define KP_S 192
#define KP_H 384          // [h(172)+pad(20) | agg(172)+pad(20)]
#define NP_G 640
#define NP_Q 768          // 516 + 200 score cols
#define NP_S 256
#define WT_K 256

// ---------------- device scratch ----------------
__device__ int   g_lastpos[NMAX];
__device__ __nv_bfloat16 g_Mh[(size_t)NPAD * KP_M];
__device__ __nv_bfloat16 g_memh[(size_t)NPAD * KP_S];
__device__ __nv_bfloat16 g_hagg[(size_t)NPAD * KP_H];    // h cols 0..191 (gate), agg cols 192..383 (wt-GEMM)
__device__ __nv_bfloat16 g_t1h[(size_t)NPAD * KP_S];     // W1cat bf16 epilogue; pad cols stay BSS-zero
__device__ __nv_bfloat16 g_wtb[(size_t)NPAD * WT_K];
__device__ __nv_bfloat16 g_QKVb[(size_t)NPAD * NP_Q];
__device__ __nv_bfloat16 g_GIb[(size_t)NMAX * G3];       // GRU input-gate pre-acts, bf16
__device__ __nv_bfloat16 g_GHb[(size_t)NMAX * G3];
__device__ __nv_bfloat16 g_BWih[KP_M * NP_G];
__device__ __nv_bfloat16 g_BWil[KP_M * NP_G];
__device__ __nv_bfloat16 g_BWhh[KP_S * NP_G];
__device__ __nv_bfloat16 g_BWhl[KP_S * NP_G];
__device__ __nv_bfloat16 g_BQh[KP_S * NP_Q];
__device__ __nv_bfloat16 g_BQl[KP_S * NP_Q];
__device__ __nv_bfloat16 g_BVh[WT_K * 256];
__device__ __nv_bfloat16 g_BVl[WT_K * 256];
__device__ __nv_bfloat16 g_BW1h[KP_H * NP_S];            // stacked [W1a; W1b]
__device__ __nv_bfloat16 g_BW1l[KP_H * NP_S];
__device__ __nv_bfloat16 g_BW2h[KP_S * NP_S];
__device__ __nv_bfloat16 g_BW2l[KP_S * NP_S];
__device__ float g_aggF[(size_t)NPAD * KP_S];
__device__ float g_emb[(size_t)NMAX * MEMD];
__device__ float g_qconst[MEMD];
__device__ float g_const2[2 * TDD];
__device__ float g_partial[RB * MEMD];

// fp32 Cody-Waite cos
__device__ __forceinline__ float cos_acc(float x) {
    float q = rintf(x * 0.15915494f);
    float r = fmaf(-q, 6.2831855f, x);
    r = fmaf(q, 1.7484555e-7f, r);
    return cosf(r);
}

__device__ __forceinline__ void split2(float x, __nv_bfloat16* hi, __nv_bfloat16* lo) {
    __nv_bfloat16 h = __float2bfloat16(x);
    *hi = h;
    *lo = __float2bfloat16(x - __bfloat162float(h));
}

// ---------------- prep kernels ----------------
__global__ void k_prep_wi_init(const float* __restrict__ Wi, int N) {
    int idx = blockIdx.x * blockDim.x + threadIdx.x;
    if (idx < N) g_lastpos[idx] = -1;
    if (idx < KP_M * NP_G) {
        int k = idx / NP_G, n = idx - k * NP_G;
        float v = (k < MSGD && n < G3) ? Wi[n * MSGD + k] : 0.f;
        split2(v, &g_BWih[idx], &g_BWil[idx]);
    }
}

__global__ void k_scatter(const int* __restrict__ src, const int* __restrict__ dst, int E) {
    int e = blockIdx.x * blockDim.x + threadIdx.x;
    if (e < E) {
        atomicMax(&g_lastpos[src[e]], e);
        atomicMax(&g_lastpos[dst[e]], E + e);
    }
}

__global__ void k_prep_wh(const float* __restrict__ Wh) {
    int idx = blockIdx.x * blockDim.x + threadIdx.x;
    if (idx < KP_S * NP_G) {
        int k = idx / NP_G, n = idx - k * NP_G;
        float v = (k < MEMD && n < G3) ? Wh[n * MEMD + k] : 0.f;
        split2(v, &g_BWhh[idx], &g_BWhl[idx]);
    }
}

__global__ void k_prep_qkv(const float* __restrict__ Wq, const float* __restrict__ Wk,
                           const float* __restrict__ Wv) {
    int idx = blockIdx.x * blockDim.x + threadIdx.x;
    if (idx >= KP_S * NP_Q) return;
    int k = idx / NP_Q, n = idx - k * NP_Q;
    float v = 0.f;
    if (k < MEMD) {
        if (n < G3) {
            int sel = n / MEMD, jj = n - sel * MEMD;
            const float* W = (sel == 0) ? Wq : ((sel == 1) ? Wk : Wv);
            v = W[k * MEMD + jj];
        } else if (n < G3 + 2 * TDD) {
            int j = n - G3;
            int hh = j / TDD, t = j - hh * TDD;
            const float* wq = Wq + (size_t)k * MEMD + hh * DHD;
            const float* wk2 = Wk + (size_t)(MEMD + t) * MEMD + hh * DHD;
            float s = 0.f;
            for (int d = 0; d < DHD; d++) s += wq[d] * wk2[d];
            v = s;
        }
    }
    split2(v, &g_BQh[idx], &g_BQl[idx]);
}

__global__ void k_prep_bv(const float* __restrict__ Wv) {
    int idx = blockIdx.x * blockDim.x + threadIdx.x;
    if (idx >= WT_K * 256) return;
    int kk = idx / 256, d = idx - kk * 256;
    float v = 0.f;
    if (kk < 2 * TDD && d < MEMD) {
        int hh = kk / TDD, t = kk - hh * TDD;
        if (d / DHD == hh) v = Wv[(size_t)(MEMD + t) * MEMD + d];
    }
    split2(v, &g_BVh[idx], &g_BVl[idx]);
}

// stacked W1: rows k<172 -> W1[k][n]; rows 192..363 -> W1[172 + (k-192)][n]; else 0
__global__ void k_prep_w1(const float* __restrict__ W1) {
    int idx = blockIdx.x * blockDim.x + threadIdx.x;
    if (idx >= KP_H * NP_S) return;
    int k = idx / NP_S, n = idx - k * NP_S;
    float v = 0.f;
    if (n < MEMD) {
        if (k < MEMD)                      v = W1[k * MEMD + n];
        else if (k >= 192 && k < 192 + MEMD) v = W1[(MEMD + k - 192) * MEMD + n];
    }
    split2(v, &g_BW1h[idx], &g_BW1l[idx]);
}

__global__ void k_prep_w2(const float* __restrict__ W2) {
    int idx = blockIdx.x * blockDim.x + threadIdx.x;
    if (idx < KP_S * NP_S) {
        int k = idx / NP_S, n = idx - k * NP_S;
        float v = (k < MEMD && n < MEMD) ? W2[k * MEMD + n] : 0.f;
        split2(v, &g_BW2h[idx], &g_BW2l[idx]);
    }
}

__global__ void k_prep_qconst(const float* __restrict__ Wq, const float* __restrict__ Wk,
                              const float* __restrict__ tb) {
    __shared__ float qc[MEMD];
    int j = threadIdx.x;
    if (j < MEMD) {
        float s = 0.f;
        for (int t = 0; t < TDD; t++)
            s += cos_acc(tb[t]) * Wq[(MEMD + t) * MEMD + j];
        qc[j] = s;
        g_qconst[j] = s;
    }
    __syncthreads();
    if (j < 2 * TDD) {
        int hh = j / TDD, t = j - hh * TDD;
        const float* wk2 = Wk + (size_t)(MEMD + t) * MEMD + hh * DHD;
        float s = 0.f;
        for (int d = 0; d < DHD; d++) s += wk2[d] * qc[hh * DHD + d];
        g_const2[j] = s;
    }
}

__global__ void k_memconv(const float* __restrict__ mem, int Nn) {
    int idx = blockIdx.x * blockDim.x + threadIdx.x;
    if (idx >= NPAD * KP_S) return;
    int n = idx / KP_S, d = idx - n * KP_S;
    float v = (n < Nn && d < MEMD) ? mem[(size_t)n * MEMD + d] : 0.f;
    g_memh[idx] = __float2bfloat16(v);
}

// ---------------- build selected message matrix ----------------
__global__ void k_build_m(const float* __restrict__ mem, const float* __restrict__ lu,
                          const float* __restrict__ ts, const float* __restrict__ ef,
                          const float* __restrict__ tw, const float* __restrict__ tb,
                          const int* __restrict__ src, const int* __restrict__ dst,
                          int Nn, int E) {
    int n = blockIdx.x;
    int tid = threadIdx.x;
    __nv_bfloat16* rh = g_Mh + (size_t)n * KP_M;
    __shared__ int s_a, s_b, s_e, s_has;
    __shared__ float s_dt;
    if (tid == 0) {
        int p = (n < Nn) ? g_lastpos[n] : -1;
        if (p < 0) {
            s_has = 0;
        } else {
            s_has = 1;
            int e, a, b;
            if (p < E) { e = p;     a = src[e]; b = dst[e]; }
            else       { e = p - E; a = dst[e]; b = src[e]; }
            s_e = e; s_a = a; s_b = b;
            s_dt = ts[e] - lu[a];
        }
    }
    __syncthreads();
    if (!s_has) {
        __nv_bfloat16 z = __float2bfloat16(0.f);
        for (int i = tid; i < KP_M; i += blockDim.x) rh[i] = z;
        return;
    }
    int a = s_a, b = s_b, e = s_e;
    float dt = s_dt;
    for (int i = tid; i < KP_M; i += blockDim.x) {
        float v = 0.f;
        if (i < MEMD)                  v = mem[(size_t)a * MEMD + i];
        else if (i < 2 * MEMD)         v = mem[(size_t)b * MEMD + (i - MEMD)];
        else if (i < 2 * MEMD + FEATD) v = ef[(size_t)e * FEATD + (i - 2 * MEMD)];
        else if (i < MSGD) { int t = i - (2 * MEMD + FEATD); v = cos_acc(dt * tw[t] + tb[t]); }
        rh[i] = __float2bfloat16(v);
    }
}

// ---------------- 2-product bf16 wmma GEMM: C (+)= Ah @ (Bh + Bl) ------------------------
#define GBK 32
#define APADS 40
#define BPADS 136
#define CPADS 132
#define SM_A0   0
#define SM_A1   10240
#define SM_BH0  20480
#define SM_BL0  29184
#define SM_BH1  37888
#define SM_BL1  46592
#define SM_TOT  55296

__global__ __launch_bounds__(256, 2) void k_gemm2(
        const __nv_bfloat16* __restrict__ Agh, int lda,
        const __nv_bfloat16* __restrict__ Bgh, const __nv_bfloat16* __restrict__ Bgl, int ldb,
        const float* __restrict__ bias, float* __restrict__ C,
        __nv_bfloat16* __restrict__ Cb, int ldcb,
        int M, int N, int Kp, int accum, int relu) {
    extern __shared__ __align__(16) unsigned char sraw[];
    __nv_bfloat16* Abuf[2] = { (__nv_bfloat16*)(sraw + SM_A0),  (__nv_bfloat16*)(sraw + SM_A1)  };
    __nv_bfloat16* Bhb[2]  = { (__nv_bfloat16*)(sraw + SM_BH0), (__nv_bfloat16*)(sraw + SM_BH1) };
    __nv_bfloat16* Blb[2]  = { (__nv_bfloat16*)(sraw + SM_BL0), (__nv_bfloat16*)(sraw + SM_BL1) };
    float* Cs = (float*)sraw;

    int tid = threadIdx.x;
    int w = tid >> 5;
    int wm = w >> 2, wn = w & 3;
    int row0 = blockIdx.y * 128;
    int col0 = blockIdx.x * 128;

    wmma::fragment<wmma::accumulator, 16, 16, 16, float> acc[4][2];
#pragma unroll
    for (int i = 0; i < 4; i++)
#pragma unroll
        for (int j = 0; j < 2; j++) wmma::fill_fragment(acc[i][j], 0.f);

    int ar = tid >> 1, akh = (tid & 1) * 16;
    int bk = tid >> 3, bns = (tid & 7) * 16;
    const __nv_bfloat16* pAh = Agh + (size_t)(row0 + ar) * lda + akh;
    const __nv_bfloat16* pBh = Bgh + (size_t)bk * ldb + col0 + bns;
    const __nv_bfloat16* pBl = Bgl + (size_t)bk * ldb + col0 + bns;
    int aoff = ar * APADS + akh;
    int boff = bk * BPADS + bns;

    {
        uint4 a0 = ((const uint4*)pAh)[0], a1 = ((const uint4*)pAh)[1];
        uint4 b0 = ((const uint4*)pBh)[0], b1 = ((const uint4*)pBh)[1];
        uint4 c0 = ((const uint4*)pBl)[0], c1 = ((const uint4*)pBl)[1];
        ((uint4*)(Abuf[0] + aoff))[0] = a0; ((uint4*)(Abuf[0] + aoff))[1] = a1;
        ((uint4*)(Bhb[0]  + boff))[0] = b0; ((uint4*)(Bhb[0]  + boff))[1] = b1;
        ((uint4*)(Blb[0]  + boff))[0] = c0; ((uint4*)(Blb[0]  + boff))[1] = c1;
    }
    __syncthreads();

    int nIter = Kp / GBK;
    for (int it = 0; it < nIter; it++) {
        int cur = it & 1, nxt = cur ^ 1;
        bool has = (it + 1 < nIter);
        uint4 rA0, rA1, rB0, rB1, rC0, rC1;
        if (has) {
            int k1 = (it + 1) * GBK;
            rA0 = ((const uint4*)(pAh + k1))[0];
            rA1 = ((const uint4*)(pAh + k1))[1];
            rB0 = ((const uint4*)(pBh + (size_t)k1 * ldb))[0];
            rB1 = ((const uint4*)(pBh + (size_t)k1 * ldb))[1];
            rC0 = ((const uint4*)(pBl + (size_t)k1 * ldb))[0];
            rC1 = ((const uint4*)(pBl + (size_t)k1 * ldb))[1];
        }
        const __nv_bfloat16* As = Abuf[cur];
        const __nv_bfloat16* Bhs = Bhb[cur];
        const __nv_bfloat16* Bls = Blb[cur];
#pragma unroll
        for (int ks = 0; ks < GBK; ks += 16) {
            wmma::fragment<wmma::matrix_b, 16, 16, 16, __nv_bfloat16, wmma::row_major> bh[2], bl[2];
            wmma::load_matrix_sync(bh[0], Bhs + ks * BPADS + wn * 32,      BPADS);
            wmma::load_matrix_sync(bh[1], Bhs + ks * BPADS + wn * 32 + 16, BPADS);
            wmma::load_matrix_sync(bl[0], Bls + ks * BPADS + wn * 32,      BPADS);
            wmma::load_matrix_sync(bl[1], Bls + ks * BPADS + wn * 32 + 16, BPADS);
#pragma unroll
            for (int im = 0; im < 4; im++) {
                wmma::fragment<wmma::matrix_a, 16, 16, 16, __nv_bfloat16, wmma::row_major> ah;
                wmma::load_matrix_sync(ah, As + (wm * 64 + im * 16) * APADS + ks, APADS);
#pragma unroll
                for (int j = 0; j < 2; j++) {
                    wmma::mma_sync(acc[im][j], ah, bh[j], acc[im][j]);
                    wmma::mma_sync(acc[im][j], ah, bl[j], acc[im][j]);
                }
            }
        }
        if (has) {
            ((uint4*)(Abuf[nxt] + aoff))[0] = rA0; ((uint4*)(Abuf[nxt] + aoff))[1] = rA1;
            ((uint4*)(Bhb[nxt]  + boff))[0] = rB0; ((uint4*)(Bhb[nxt]  + boff))[1] = rB1;
            ((uint4*)(Blb[nxt]  + boff))[0] = rC0; ((uint4*)(Blb[nxt]  + boff))[1] = rC1;
        }
        __syncthreads();
    }

    for (int ph = 0; ph < 2; ph++) {
        if (wm == ph) {
#pragma unroll
            for (int im = 0; im < 4; im++)
#pragma unroll
                for (int j = 0; j < 2; j++)
                    wmma::store_matrix_sync(Cs + (im * 16) * CPADS + wn * 32 + j * 16,
                                            acc[im][j], CPADS, wmma::mem_row_major);
        }
        __syncthreads();
        for (int e = tid; e < 64 * 128; e += 256) {
            int rr = e >> 7, cc = e & 127;
            int gr = row0 + ph * 64 + rr, gc = col0 + cc;
            if (gr < M && gc < N) {
                float v = Cs[rr * CPADS + cc];
                if (bias) v += bias[gc];
                if (accum) v += C[(size_t)gr * N + gc];
                if (relu) v = fmaxf(v, 0.f);
                if (Cb) Cb[(size_t)gr * ldcb + gc] = __float2bfloat16(v);
                else    C[(size_t)gr * N + gc] = v;
            }
        }
        __syncthreads();
    }
}

// ---------------- GRU gating (bf16 GI/GH reads) + h -> hagg cols 0..191 ----------------
__global__ void k_gate(const float* __restrict__ mem, const float* __restrict__ nf, int Nn) {
    int idx = blockIdx.x * blockDim.x + threadIdx.x;
    if (idx >= NPAD * KP_S) return;
    int n = idx / KP_S, d = idx - n * KP_S;
    float out = 0.f;
    if (n < Nn && d < MEMD) {
        size_t mi = (size_t)n * MEMD + d;
        float mv = mem[mi];
        float hv;
        if (g_lastpos[n] >= 0) {
            const __nv_bfloat16* gi = g_GIb + (size_t)n * G3;
            const __nv_bfloat16* gh = g_GHb + (size_t)n * G3;
            float r = 1.f / (1.f + expf(-(__bfloat162float(gi[d]) + __bfloat162float(gh[d]))));
            float z = 1.f / (1.f + expf(-(__bfloat162float(gi[MEMD + d]) + __bfloat162float(gh[MEMD + d]))));
            float g = tanhf(__bfloat162float(gi[2 * MEMD + d]) +
                            r * __bfloat162float(gh[2 * MEMD + d]));
            hv = (1.f - z) * g + z * mv;
        } else {
            hv = mv;
        }
        out = hv + nf[mi];
    }
    g_hagg[(size_t)n * KP_H + d] = __float2bfloat16(out);
}

// ---------------- temporal attention (bf16 vectorized gathers) ----------------
__global__ void k_attn(const int* __restrict__ nbi, const float* __restrict__ nts,
                       const float* __restrict__ tw, const float* __restrict__ tb,
                       const float* __restrict__ ts, int Nn, int E) {
    int n = blockIdx.x;
    int tid = threadIdx.x;
    if (n >= Nn) {
        __nv_bfloat16 z = __float2bfloat16(0.f);
        for (int d = tid; d < WT_K; d += blockDim.x) g_wtb[(size_t)n * WT_K + d] = z;
        for (int d = tid; d < KP_S; d += blockDim.x) g_aggF[(size_t)n * KP_S + d] = 0.f;
        return;
    }
    __shared__ float s_q[MEMD];
    __shared__ float s_c[2 * TDD];
    __shared__ float s_te[KNB * TDD];
    __shared__ float s_sc[2 * KNB];
    __shared__ float s_at[2 * KNB];
    __shared__ int s_nb[KNB];

    const __nv_bfloat16* qrow = g_QKVb + (size_t)n * NP_Q;
    float t_now = __ldg(&ts[E - 1]);

    if (tid < KNB) s_nb[tid] = nbi[(size_t)n * KNB + tid];
    for (int i = tid; i < MEMD; i += blockDim.x)
        s_q[i] = __bfloat162float(qrow[i]) + g_qconst[i];
    for (int j = tid; j < 2 * TDD; j += blockDim.x)
        s_c[j] = __bfloat162float(qrow[G3 + j]) + g_const2[j];
    for (int j = tid; j < KNB * TDD; j += blockDim.x) {
        int k = j / TDD, t = j - k * TDD;
        float dt = t_now - nts[(size_t)n * KNB + k];
        s_te[j] = cos_acc(dt * tw[t] + tb[t]);
    }
    __syncthreads();

    int wid = tid >> 5, lane = tid & 31;
    for (int p = wid; p < 2 * KNB; p += 4) {
        int k = p >> 1, hh = p & 1;
        // k-row gather as bf16x2 (offset MEMD + hh*DHD is even)
        const __nv_bfloat162* kr2 =
            (const __nv_bfloat162*)(g_QKVb + (size_t)s_nb[k] * NP_Q + MEMD + hh * DHD);
        const float* qq = s_q + hh * DHD;
        float s = 0.f;
        for (int d2 = lane; d2 < DHD / 2; d2 += 32) {
            __nv_bfloat162 kv = kr2[d2];
            s += qq[2 * d2] * __bfloat162float(kv.x) + qq[2 * d2 + 1] * __bfloat162float(kv.y);
        }
        const float* cc = s_c + hh * TDD;
        const float* te = s_te + k * TDD;
        for (int t = lane; t < TDD; t += 32) s += cc[t] * te[t];
        for (int o = 16; o; o >>= 1) s += __shfl_down_sync(0xffffffffu, s, o);
        if (lane == 0) s_sc[hh * KNB + k] = s * 0.10783277320343841f;  // 1/sqrt(86)
    }
    __syncthreads();

    if (tid < 2) {
        float mx = -1e30f;
        for (int k = 0; k < KNB; k++) mx = fmaxf(mx, s_sc[tid * KNB + k]);
        float sum = 0.f;
        for (int k = 0; k < KNB; k++) {
            float e = expf(s_sc[tid * KNB + k] - mx);
            s_at[tid * KNB + k] = e;
            sum += e;
        }
        float inv = 1.f / sum;
        for (int k = 0; k < KNB; k++) s_at[tid * KNB + k] *= inv;
    }
    __syncthreads();

    for (int j = tid; j < WT_K; j += blockDim.x) {
        float s = 0.f;
        if (j < 2 * TDD) {
            int hh = j / TDD, t = j - hh * TDD;
            for (int k = 0; k < KNB; k++) s += s_at[hh * KNB + k] * s_te[k * TDD + t];
        }
        g_wtb[(size_t)n * WT_K + j] = __float2bfloat16(s);
    }

    // v-gather as bf16x2: pair d = 2*d2, 2*d2+1 (DHD even => pairs never straddle heads)
    for (int d2 = tid; d2 < KP_S / 2; d2 += blockDim.x) {
        float s0 = 0.f, s1 = 0.f;
        int d = 2 * d2;
        if (d < MEMD) {
            int hh = d / DHD;
            for (int k = 0; k < KNB; k++) {
                __nv_bfloat162 vv = *(const __nv_bfloat162*)(
                    g_QKVb + (size_t)s_nb[k] * NP_Q + 2 * MEMD + d);
                float a = s_at[hh * KNB + k];
                s0 += a * __bfloat162float(vv.x);
                if (d + 1 < MEMD) s1 += a * __bfloat162float(vv.y);
            }
        }
        g_aggF[(size_t)n * KP_S + d] = s0;
        g_aggF[(size_t)n * KP_S + d + 1] = s1;
    }
}

// ---------------- deterministic final reduction + classifier ----------------
__global__ void k_reduce1(int Nn) {
    int b = blockIdx.x, c = threadIdx.x;
    if (c >= MEMD) return;
    float s = 0.f;
    for (int r = 1 + b; r < Nn; r += RB) s += g_emb[(size_t)r * MEMD + c];
    g_partial[b * MEMD + c] = s;
}

__global__ void k_final(const float* __restrict__ fc2w, const float* __restrict__ fc2b,
                        float* __restrict__ out, int Nn) {
    __shared__ float tm[MEMD];
    int c = threadIdx.x;
    if (c < MEMD) {
        float s = 0.f;
        for (int b = 0; b < RB; b++) s += g_partial[b * MEMD + c];
        tm[c] = tanhf(s / (float)(Nn - 1));
    }
    __syncthreads();
    if (c == 0) {
        float l0 = fc2b[0], l1 = fc2b[1];
        for (int i = 0; i < MEMD; i++) {
            l0 += tm[i] * fc2w[i * 2 + 0];
            l1 += tm[i] * fc2w[i * 2 + 1];
        }
        float mx = fmaxf(l0, l1);
        float e0 = expf(l0 - mx), e1 = expf(l1 - mx);
        float inv = 1.f / (e0 + e1);
        out[0] = e0 * inv;
        out[1] = e1 * inv;
    }
}

// ---------------- host orchestration ----------------
extern "C" void kernel_launch(void* const* d_in, const int* in_sizes, int n_in,
                              void* d_out, int out_size) {
    const float* node_features = (const float*)d_in[0];
    const float* memory        = (const float*)d_in[1];
    const float* last_update   = (const float*)d_in[2];
    const float* timestamps    = (const float*)d_in[3];
    const float* edge_features = (const float*)d_in[4];
    const float* neighbor_ts   = (const float*)d_in[5];
    const float* time_w        = (const float*)d_in[6];
    const float* time_b        = (const float*)d_in[7];
    const float* gru_Wi        = (const float*)d_in[8];
    const float* gru_Wh        = (const float*)d_in[9];
    const float* gru_bi        = (const float*)d_in[10];
    const float* gru_bh        = (const float*)d_in[11];
    const float* Wq            = (const float*)d_in[12];
    const float* Wk            = (const float*)d_in[13];
    const float* Wv            = (const float*)d_in[14];
    const float* W1            = (const float*)d_in[15];
    const float* b1            = (const float*)d_in[16];
    const float* W2            = (const float*)d_in[17];
    const float* b2            = (const float*)d_in[18];
    const float* fc2_w         = (const float*)d_in[19];
    const float* fc2_b         = (const float*)d_in[20];
    const int*   sources       = (const int*)d_in[21];
    const int*   destinations  = (const int*)d_in[22];
    const int*   neighbor_idx  = (const int*)d_in[23];

    int N = in_sizes[0] / FEATD;
    int E = in_sizes[3];
    int MtRows = NPAD / 128;

    static int s_attr_done = 0;
    if (!s_attr_done) {
        cudaFuncSetAttribute(k_gemm2, cudaFuncAttributeMaxDynamicSharedMemorySize, SM_TOT);
        s_attr_done = 1;
    }

    __nv_bfloat16 *pMh, *pMemh, *pHagg, *pT1h, *pWtb, *pQKVb, *pGIb, *pGHb;
    __nv_bfloat16 *pWih, *pWil, *pWhh, *pWhl, *pQh, *pQl, *pBVh, *pBVl;
    __nv_bfloat16 *pW1h, *pW1l, *pW2h, *pW2l;
    float *pAggF, *pEmb;
    cudaGetSymbolAddress((void**)&pMh,   g_Mh);
    cudaGetSymbolAddress((void**)&pMemh, g_memh);
    cudaGetSymbolAddress((void**)&pHagg, g_hagg);
    cudaGetSymbolAddress((void**)&pT1h,  g_t1h);
    cudaGetSymbolAddress((void**)&pWtb,  g_wtb);
    cudaGetSymbolAddress((void**)&pQKVb, g_QKVb);
    cudaGetSymbolAddress((void**)&pGIb,  g_GIb);
    cudaGetSymbolAddress((void**)&pGHb,  g_GHb);
    cudaGetSymbolAddress((void**)&pWih,  g_BWih);
    cudaGetSymbolAddress((void**)&pWil,  g_BWil);
    cudaGetSymbolAddress((void**)&pWhh,  g_BWhh);
    cudaGetSymbolAddress((void**)&pWhl,  g_BWhl);
    cudaGetSymbolAddress((void**)&pQh,   g_BQh);
    cudaGetSymbolAddress((void**)&pQl,   g_BQl);
    cudaGetSymbolAddress((void**)&pBVh,  g_BVh);
    cudaGetSymbolAddress((void**)&pBVl,  g_BVl);
    cudaGetSymbolAddress((void**)&pW1h,  g_BW1h);
    cudaGetSymbolAddress((void**)&pW1l,  g_BW1l);
    cudaGetSymbolAddress((void**)&pW2h,  g_BW2h);
    cudaGetSymbolAddress((void**)&pW2l,  g_BW2l);
    cudaGetSymbolAddress((void**)&pAggF, g_aggF);
    cudaGetSymbolAddress((void**)&pEmb,  g_emb);

    // GI GEMM at my-index 3 (ncu -s 5)
    k_prep_wi_init<<<(KP_M * NP_G + 255) / 256, 256>>>(gru_Wi, N);
    k_scatter<<<(E + 255) / 256, 256>>>(sources, destinations, E);
    k_build_m<<<NPAD, 128>>>(memory, last_update, timestamps, edge_features,
                             time_w, time_b, sources, destinations, N, E);
    k_gemm2<<<dim3(5, MtRows), 256, SM_TOT>>>(pMh, KP_M, pWih, pWil, NP_G,
                                              gru_bi, nullptr, pGIb, G3,
                                              N, G3, KP_M, 0, 0);
    k_memconv<<<(NPAD * KP_S + 255) / 256, 256>>>(memory, N);
    k_prep_wh<<<(KP_S * NP_G + 255) / 256, 256>>>(gru_Wh);
    k_gemm2<<<dim3(5, MtRows), 256, SM_TOT>>>(pMemh, KP_S, pWhh, pWhl, NP_G,
                                              gru_bh, nullptr, pGHb, G3,
                                              N, G3, KP_S, 0, 0);
    k_gate<<<(NPAD * KP_S + 255) / 256, 256>>>(memory, node_features, N);

    // extended QKV = h @ [Wq1|Wk1|Wv1|Wc] -> bf16 (reads hagg h-part, lda=384)
    k_prep_qkv<<<(KP_S * NP_Q + 255) / 256, 256>>>(Wq, Wk, Wv);
    k_gemm2<<<dim3(6, MtRows), 256, SM_TOT>>>(pHagg, KP_H, pQh, pQl, NP_Q,
                                              nullptr, nullptr, pQKVb, NP_Q,
                                              N, NP_Q, KP_S, 0, 0);

    // attention
    k_prep_qconst<<<1, 256>>>(Wq, Wk, time_b);
    k_prep_bv<<<(WT_K * 256 + 255) / 256, 256>>>(Wv);
    k_attn<<<NPAD, 128>>>(neighbor_idx, neighbor_ts, time_w, time_b,
                          timestamps, N, E);
    // agg = aggF + wt @ Wv2blk -> bf16 into hagg cols 192..383
    k_gemm2<<<dim3(2, MtRows), 256, SM_TOT>>>(pWtb, WT_K, pBVh, pBVl, 256,
                                              nullptr, pAggF, pHagg + 192, KP_H,
                                              NPAD, KP_S, WT_K, 1, 0);

    // MLP: t1h = bf16(relu(hagg @ W1cat + b1)); emb = t1 @ W2 + b2
    k_prep_w1<<<(KP_H * NP_S + 255) / 256, 256>>>(W1);
    k_prep_w2<<<(KP_S * NP_S + 255) / 256, 256>>>(W2);
    k_gemm2<<<dim3(2, MtRows), 256, SM_TOT>>>(pHagg, KP_H, pW1h, pW1l, NP_S,
                                              b1, nullptr, pT1h, KP_S,
                                              N, MEMD, KP_H, 0, 1);
    k_gemm2<<<dim3(2, MtRows), 256, SM_TOT>>>(pT1h, KP_S, pW2h, pW2l, NP_S,
                                              b2, pEmb, nullptr, 0, N, MEMD, KP_S, 0, 0);

    // classifier head
    k_reduce1<<<RB, 192>>>(N);
    k_final<<<1, 192>>>(fc2_w, fc2_b, (float*)d_out, N);
}

// round 16
// speedup vs baseline: 2.5026x; 1.3357x over previous
#include <cuda_runtime.h>
#include <cuda_bf16.h>
#include <mma.h>
#include <math.h>

using namespace nvcuda;

#define MEMD 172
#define FEATD 172
#define TDD 100
#define KNB 10
#define DHD 86
#define MSGD 616          // 2*MEM + FEAT + TD
#define G3 516            // 3*MEM
#define NMAX 100000
#define NPAD 100096
#define RB 256

// padded strides
#define KP_M 640
#define KP_S 192
#define KP_H 384          // [h(172)+pad(20) | agg(172)+pad(20)]
#define NP_G 640
#define NP_Q 768          // 516 + 200 score cols
#define NP_S 256
#define WT_K 256

// ---------------- device scratch ----------------
__device__ int   g_lastpos[NMAX];
__device__ __nv_bfloat16 g_Mh[(size_t)NPAD * KP_M];
__device__ __nv_bfloat16 g_memh[(size_t)NPAD * KP_S];
__device__ __nv_bfloat16 g_hagg[(size_t)NPAD * KP_H];    // h cols 0..191 (gate), agg cols 192..383 (wt-GEMM)
__device__ __nv_bfloat16 g_t1h[(size_t)NPAD * KP_S];     // W1cat bf16 epilogue; pad cols stay BSS-zero
__device__ __nv_bfloat16 g_wtb[(size_t)NPAD * WT_K];
__device__ __nv_bfloat16 g_QKVb[(size_t)NPAD * NP_Q];
__device__ __nv_bfloat16 g_GIb[(size_t)NMAX * G3];
__device__ __nv_bfloat16 g_GHb[(size_t)NMAX * G3];
// single-plane bf16 weight buffers
__device__ __nv_bfloat16 g_BWih[KP_M * NP_G];
__device__ __nv_bfloat16 g_BWhh[KP_S * NP_G];
__device__ __nv_bfloat16 g_BQh[KP_S * NP_Q];
__device__ __nv_bfloat16 g_BVh[WT_K * 256];
__device__ __nv_bfloat16 g_BW1h[KP_H * NP_S];
__device__ __nv_bfloat16 g_BW2h[KP_S * NP_S];
__device__ float g_aggF[(size_t)NPAD * KP_S];
__device__ float g_emb[(size_t)NMAX * MEMD];
__device__ float g_qconst[MEMD];
__device__ float g_const2[2 * TDD];
__device__ float g_partial[RB * MEMD];

// fp32 Cody-Waite cos
__device__ __forceinline__ float cos_acc(float x) {
    float q = rintf(x * 0.15915494f);
    float r = fmaf(-q, 6.2831855f, x);
    r = fmaf(q, 1.7484555e-7f, r);
    return cosf(r);
}

// ---------------- prep kernels ----------------
__global__ void k_prep_wi_init(const float* __restrict__ Wi, int N) {
    int idx = blockIdx.x * blockDim.x + threadIdx.x;
    if (idx < N) g_lastpos[idx] = -1;
    if (idx < KP_M * NP_G) {
        int k = idx / NP_G, n = idx - k * NP_G;
        float v = (k < MSGD && n < G3) ? Wi[n * MSGD + k] : 0.f;
        g_BWih[idx] = __float2bfloat16(v);
    }
}

__global__ void k_scatter(const int* __restrict__ src, const int* __restrict__ dst, int E) {
    int e = blockIdx.x * blockDim.x + threadIdx.x;
    if (e < E) {
        atomicMax(&g_lastpos[src[e]], e);
        atomicMax(&g_lastpos[dst[e]], E + e);
    }
}

__global__ void k_prep_wh(const float* __restrict__ Wh) {
    int idx = blockIdx.x * blockDim.x + threadIdx.x;
    if (idx < KP_S * NP_G) {
        int k = idx / NP_G, n = idx - k * NP_G;
        float v = (k < MEMD && n < G3) ? Wh[n * MEMD + k] : 0.f;
        g_BWhh[idx] = __float2bfloat16(v);
    }
}

__global__ void k_prep_qkv(const float* __restrict__ Wq, const float* __restrict__ Wk,
                           const float* __restrict__ Wv) {
    int idx = blockIdx.x * blockDim.x + threadIdx.x;
    if (idx >= KP_S * NP_Q) return;
    int k = idx / NP_Q, n = idx - k * NP_Q;
    float v = 0.f;
    if (k < MEMD) {
        if (n < G3) {
            int sel = n / MEMD, jj = n - sel * MEMD;
            const float* W = (sel == 0) ? Wq : ((sel == 1) ? Wk : Wv);
            v = W[k * MEMD + jj];
        } else if (n < G3 + 2 * TDD) {
            int j = n - G3;
            int hh = j / TDD, t = j - hh * TDD;
            const float* wq = Wq + (size_t)k * MEMD + hh * DHD;
            const float* wk2 = Wk + (size_t)(MEMD + t) * MEMD + hh * DHD;
            float s = 0.f;
            for (int d = 0; d < DHD; d++) s += wq[d] * wk2[d];
            v = s;
        }
    }
    g_BQh[idx] = __float2bfloat16(v);
}

__global__ void k_prep_bv(const float* __restrict__ Wv) {
    int idx = blockIdx.x * blockDim.x + threadIdx.x;
    if (idx >= WT_K * 256) return;
    int kk = idx / 256, d = idx - kk * 256;
    float v = 0.f;
    if (kk < 2 * TDD && d < MEMD) {
        int hh = kk / TDD, t = kk - hh * TDD;
        if (d / DHD == hh) v = Wv[(size_t)(MEMD + t) * MEMD + d];
    }
    g_BVh[idx] = __float2bfloat16(v);
}

// stacked W1: rows k<172 -> W1[k][n]; rows 192..363 -> W1[172 + (k-192)][n]; else 0
__global__ void k_prep_w1(const float* __restrict__ W1) {
    int idx = blockIdx.x * blockDim.x + threadIdx.x;
    if (idx >= KP_H * NP_S) return;
    int k = idx / NP_S, n = idx - k * NP_S;
    float v = 0.f;
    if (n < MEMD) {
        if (k < MEMD)                        v = W1[k * MEMD + n];
        else if (k >= 192 && k < 192 + MEMD) v = W1[(MEMD + k - 192) * MEMD + n];
    }
    g_BW1h[idx] = __float2bfloat16(v);
}

__global__ void k_prep_w2(const float* __restrict__ W2) {
    int idx = blockIdx.x * blockDim.x + threadIdx.x;
    if (idx < KP_S * NP_S) {
        int k = idx / NP_S, n = idx - k * NP_S;
        float v = (k < MEMD && n < MEMD) ? W2[k * MEMD + n] : 0.f;
        g_BW2h[idx] = __float2bfloat16(v);
    }
}

__global__ void k_prep_qconst(const float* __restrict__ Wq, const float* __restrict__ Wk,
                              const float* __restrict__ tb) {
    __shared__ float qc[MEMD];
    int j = threadIdx.x;
    if (j < MEMD) {
        float s = 0.f;
        for (int t = 0; t < TDD; t++)
            s += cos_acc(tb[t]) * Wq[(MEMD + t) * MEMD + j];
        qc[j] = s;
        g_qconst[j] = s;
    }
    __syncthreads();
    if (j < 2 * TDD) {
        int hh = j / TDD, t = j - hh * TDD;
        const float* wk2 = Wk + (size_t)(MEMD + t) * MEMD + hh * DHD;
        float s = 0.f;
        for (int d = 0; d < DHD; d++) s += wk2[d] * qc[hh * DHD + d];
        g_const2[j] = s;
    }
}

__global__ void k_memconv(const float* __restrict__ mem, int Nn) {
    int idx = blockIdx.x * blockDim.x + threadIdx.x;
    if (idx >= NPAD * KP_S) return;
    int n = idx / KP_S, d = idx - n * KP_S;
    float v = (n < Nn && d < MEMD) ? mem[(size_t)n * MEMD + d] : 0.f;
    g_memh[idx] = __float2bfloat16(v);
}

// ---------------- build selected message matrix ----------------
__global__ void k_build_m(const float* __restrict__ mem, const float* __restrict__ lu,
                          const float* __restrict__ ts, const float* __restrict__ ef,
                          const float* __restrict__ tw, const float* __restrict__ tb,
                          const int* __restrict__ src, const int* __restrict__ dst,
                          int Nn, int E) {
    int n = blockIdx.x;
    int tid = threadIdx.x;
    __nv_bfloat16* rh = g_Mh + (size_t)n * KP_M;
    __shared__ int s_a, s_b, s_e, s_has;
    __shared__ float s_dt;
    if (tid == 0) {
        int p = (n < Nn) ? g_lastpos[n] : -1;
        if (p < 0) {
            s_has = 0;
        } else {
            s_has = 1;
            int e, a, b;
            if (p < E) { e = p;     a = src[e]; b = dst[e]; }
            else       { e = p - E; a = dst[e]; b = src[e]; }
            s_e = e; s_a = a; s_b = b;
            s_dt = ts[e] - lu[a];
        }
    }
    __syncthreads();
    if (!s_has) {
        __nv_bfloat16 z = __float2bfloat16(0.f);
        for (int i = tid; i < KP_M; i += blockDim.x) rh[i] = z;
        return;
    }
    int a = s_a, b = s_b, e = s_e;
    float dt = s_dt;
    for (int i = tid; i < KP_M; i += blockDim.x) {
        float v = 0.f;
        if (i < MEMD)                  v = mem[(size_t)a * MEMD + i];
        else if (i < 2 * MEMD)         v = mem[(size_t)b * MEMD + (i - MEMD)];
        else if (i < 2 * MEMD + FEATD) v = ef[(size_t)e * FEATD + (i - 2 * MEMD)];
        else if (i < MSGD) { int t = i - (2 * MEMD + FEATD); v = cos_acc(dt * tw[t] + tb[t]); }
        rh[i] = __float2bfloat16(v);
    }
}

// ---------------- single-product bf16 wmma GEMM: C (+)= Ah @ Bh ------------------------
// 128x128 block, BK=32, 8 warps (2x4), warp tile 64x32, double-buffered smem,
// reg prefetch, 1 sync/iter, 2 CTAs/SM. Epilogue: bias/accum/relu, fp32 or bf16 out.
#define GBK 32
#define APADS 40
#define BPADS 136
#define CPADS 132
#define SM_A0   0
#define SM_A1   10240
#define SM_BH0  20480
#define SM_BH1  29184
#define SM_TOT  37888     // Cs overlay 33792 <= SM_TOT

__global__ __launch_bounds__(256, 2) void k_gemm1(
        const __nv_bfloat16* __restrict__ Agh, int lda,
        const __nv_bfloat16* __restrict__ Bgh, int ldb,
        const float* __restrict__ bias, float* __restrict__ C,
        __nv_bfloat16* __restrict__ Cb, int ldcb,
        int M, int N, int Kp, int accum, int relu) {
    extern __shared__ __align__(16) unsigned char sraw[];
    __nv_bfloat16* Abuf[2] = { (__nv_bfloat16*)(sraw + SM_A0),  (__nv_bfloat16*)(sraw + SM_A1)  };
    __nv_bfloat16* Bhb[2]  = { (__nv_bfloat16*)(sraw + SM_BH0), (__nv_bfloat16*)(sraw + SM_BH1) };
    float* Cs = (float*)sraw;

    int tid = threadIdx.x;
    int w = tid >> 5;
    int wm = w >> 2, wn = w & 3;
    int row0 = blockIdx.y * 128;
    int col0 = blockIdx.x * 128;

    wmma::fragment<wmma::accumulator, 16, 16, 16, float> acc[4][2];
#pragma unroll
    for (int i = 0; i < 4; i++)
#pragma unroll
        for (int j = 0; j < 2; j++) wmma::fill_fragment(acc[i][j], 0.f);

    int ar = tid >> 1, akh = (tid & 1) * 16;
    int bk = tid >> 3, bns = (tid & 7) * 16;
    const __nv_bfloat16* pAh = Agh + (size_t)(row0 + ar) * lda + akh;
    const __nv_bfloat16* pBh = Bgh + (size_t)bk * ldb + col0 + bns;
    int aoff = ar * APADS + akh;
    int boff = bk * BPADS + bns;

    {
        uint4 a0 = ((const uint4*)pAh)[0], a1 = ((const uint4*)pAh)[1];
        uint4 b0 = ((const uint4*)pBh)[0], b1 = ((const uint4*)pBh)[1];
        ((uint4*)(Abuf[0] + aoff))[0] = a0; ((uint4*)(Abuf[0] + aoff))[1] = a1;
        ((uint4*)(Bhb[0]  + boff))[0] = b0; ((uint4*)(Bhb[0]  + boff))[1] = b1;
    }
    __syncthreads();

    int nIter = Kp / GBK;
    for (int it = 0; it < nIter; it++) {
        int cur = it & 1, nxt = cur ^ 1;
        bool has = (it + 1 < nIter);
        uint4 rA0, rA1, rB0, rB1;
        if (has) {
            int k1 = (it + 1) * GBK;
            rA0 = ((const uint4*)(pAh + k1))[0];
            rA1 = ((const uint4*)(pAh + k1))[1];
            rB0 = ((const uint4*)(pBh + (size_t)k1 * ldb))[0];
            rB1 = ((const uint4*)(pBh + (size_t)k1 * ldb))[1];
        }
        const __nv_bfloat16* As = Abuf[cur];
        const __nv_bfloat16* Bhs = Bhb[cur];
#pragma unroll
        for (int ks = 0; ks < GBK; ks += 16) {
            wmma::fragment<wmma::matrix_b, 16, 16, 16, __nv_bfloat16, wmma::row_major> bh[2];
            wmma::load_matrix_sync(bh[0], Bhs + ks * BPADS + wn * 32,      BPADS);
            wmma::load_matrix_sync(bh[1], Bhs + ks * BPADS + wn * 32 + 16, BPADS);
#pragma unroll
            for (int im = 0; im < 4; im++) {
                wmma::fragment<wmma::matrix_a, 16, 16, 16, __nv_bfloat16, wmma::row_major> ah;
                wmma::load_matrix_sync(ah, As + (wm * 64 + im * 16) * APADS + ks, APADS);
                wmma::mma_sync(acc[im][0], ah, bh[0], acc[im][0]);
                wmma::mma_sync(acc[im][1], ah, bh[1], acc[im][1]);
            }
        }
        if (has) {
            ((uint4*)(Abuf[nxt] + aoff))[0] = rA0; ((uint4*)(Abuf[nxt] + aoff))[1] = rA1;
            ((uint4*)(Bhb[nxt]  + boff))[0] = rB0; ((uint4*)(Bhb[nxt]  + boff))[1] = rB1;
        }
        __syncthreads();
    }

    for (int ph = 0; ph < 2; ph++) {
        if (wm == ph) {
#pragma unroll
            for (int im = 0; im < 4; im++)
#pragma unroll
                for (int j = 0; j < 2; j++)
                    wmma::store_matrix_sync(Cs + (im * 16) * CPADS + wn * 32 + j * 16,
                                            acc[im][j], CPADS, wmma::mem_row_major);
        }
        __syncthreads();
        for (int e = tid; e < 64 * 128; e += 256) {
            int rr = e >> 7, cc = e & 127;
            int gr = row0 + ph * 64 + rr, gc = col0 + cc;
            if (gr < M && gc < N) {
                float v = Cs[rr * CPADS + cc];
                if (bias) v += bias[gc];
                if (accum) v += C[(size_t)gr * N + gc];
                if (relu) v = fmaxf(v, 0.f);
                if (Cb) Cb[(size_t)gr * ldcb + gc] = __float2bfloat16(v);
                else    C[(size_t)gr * N + gc] = v;
            }
        }
        __syncthreads();
    }
}

// ---------------- GRU gating (bf16 GI/GH reads) + h -> hagg cols 0..191 ----------------
__global__ void k_gate(const float* __restrict__ mem, const float* __restrict__ nf, int Nn) {
    int idx = blockIdx.x * blockDim.x + threadIdx.x;
    if (idx >= NPAD * KP_S) return;
    int n = idx / KP_S, d = idx - n * KP_S;
    float out = 0.f;
    if (n < Nn && d < MEMD) {
        size_t mi = (size_t)n * MEMD + d;
        float mv = mem[mi];
        float hv;
        if (g_lastpos[n] >= 0) {
            const __nv_bfloat16* gi = g_GIb + (size_t)n * G3;
            const __nv_bfloat16* gh = g_GHb + (size_t)n * G3;
            float r = 1.f / (1.f + expf(-(__bfloat162float(gi[d]) + __bfloat162float(gh[d]))));
            float z = 1.f / (1.f + expf(-(__bfloat162float(gi[MEMD + d]) + __bfloat162float(gh[MEMD + d]))));
            float g = tanhf(__bfloat162float(gi[2 * MEMD + d]) +
                            r * __bfloat162float(gh[2 * MEMD + d]));
            hv = (1.f - z) * g + z * mv;
        } else {
            hv = mv;
        }
        out = hv + nf[mi];
    }
    g_hagg[(size_t)n * KP_H + d] = __float2bfloat16(out);
}

// ---------------- temporal attention (bf16 vectorized gathers) ----------------
__global__ void k_attn(const int* __restrict__ nbi, const float* __restrict__ nts,
                       const float* __restrict__ tw, const float* __restrict__ tb,
                       const float* __restrict__ ts, int Nn, int E) {
    int n = blockIdx.x;
    int tid = threadIdx.x;
    if (n >= Nn) {
        __nv_bfloat16 z = __float2bfloat16(0.f);
        for (int d = tid; d < WT_K; d += blockDim.x) g_wtb[(size_t)n * WT_K + d] = z;
        for (int d = tid; d < KP_S; d += blockDim.x) g_aggF[(size_t)n * KP_S + d] = 0.f;
        return;
    }
    __shared__ float s_q[MEMD];
    __shared__ float s_c[2 * TDD];
    __shared__ float s_te[KNB * TDD];
    __shared__ float s_sc[2 * KNB];
    __shared__ float s_at[2 * KNB];
    __shared__ int s_nb[KNB];

    const __nv_bfloat16* qrow = g_QKVb + (size_t)n * NP_Q;
    float t_now = __ldg(&ts[E - 1]);

    if (tid < KNB) s_nb[tid] = nbi[(size_t)n * KNB + tid];
    for (int i = tid; i < MEMD; i += blockDim.x)
        s_q[i] = __bfloat162float(qrow[i]) + g_qconst[i];
    for (int j = tid; j < 2 * TDD; j += blockDim.x)
        s_c[j] = __bfloat162float(qrow[G3 + j]) + g_const2[j];
    for (int j = tid; j < KNB * TDD; j += blockDim.x) {
        int k = j / TDD, t = j - k * TDD;
        float dt = t_now - nts[(size_t)n * KNB + k];
        s_te[j] = cos_acc(dt * tw[t] + tb[t]);
    }
    __syncthreads();

    int wid = tid >> 5, lane = tid & 31;
    for (int p = wid; p < 2 * KNB; p += 4) {
        int k = p >> 1, hh = p & 1;
        const __nv_bfloat162* kr2 =
            (const __nv_bfloat162*)(g_QKVb + (size_t)s_nb[k] * NP_Q + MEMD + hh * DHD);
        const float* qq = s_q + hh * DHD;
        float s = 0.f;
        for (int d2 = lane; d2 < DHD / 2; d2 += 32) {
            __nv_bfloat162 kv = kr2[d2];
            s += qq[2 * d2] * __bfloat162float(kv.x) + qq[2 * d2 + 1] * __bfloat162float(kv.y);
        }
        const float* cc = s_c + hh * TDD;
        const float* te = s_te + k * TDD;
        for (int t = lane; t < TDD; t += 32) s += cc[t] * te[t];
        for (int o = 16; o; o >>= 1) s += __shfl_down_sync(0xffffffffu, s, o);
        if (lane == 0) s_sc[hh * KNB + k] = s * 0.10783277320343841f;  // 1/sqrt(86)
    }
    __syncthreads();

    if (tid < 2) {
        float mx = -1e30f;
        for (int k = 0; k < KNB; k++) mx = fmaxf(mx, s_sc[tid * KNB + k]);
        float sum = 0.f;
        for (int k = 0; k < KNB; k++) {
            float e = expf(s_sc[tid * KNB + k] - mx);
            s_at[tid * KNB + k] = e;
            sum += e;
        }
        float inv = 1.f / sum;
        for (int k = 0; k < KNB; k++) s_at[tid * KNB + k] *= inv;
    }
    __syncthreads();

    for (int j = tid; j < WT_K; j += blockDim.x) {
        float s = 0.f;
        if (j < 2 * TDD) {
            int hh = j / TDD, t = j - hh * TDD;
            for (int k = 0; k < KNB; k++) s += s_at[hh * KNB + k] * s_te[k * TDD + t];
        }
        g_wtb[(size_t)n * WT_K + j] = __float2bfloat16(s);
    }

    for (int d2 = tid; d2 < KP_S / 2; d2 += blockDim.x) {
        float s0 = 0.f, s1 = 0.f;
        int d = 2 * d2;
        if (d < MEMD) {
            int hh = d / DHD;
            for (int k = 0; k < KNB; k++) {
                __nv_bfloat162 vv = *(const __nv_bfloat162*)(
                    g_QKVb + (size_t)s_nb[k] * NP_Q + 2 * MEMD + d);
                float a = s_at[hh * KNB + k];
                s0 += a * __bfloat162float(vv.x);
                if (d + 1 < MEMD) s1 += a * __bfloat162float(vv.y);
            }
        }
        g_aggF[(size_t)n * KP_S + d] = s0;
        g_aggF[(size_t)n * KP_S + d + 1] = s1;
    }
}

// ---------------- deterministic final reduction + classifier ----------------
__global__ void k_reduce1(int Nn) {
    int b = blockIdx.x, c = threadIdx.x;
    if (c >= MEMD) return;
    float s = 0.f;
    for (int r = 1 + b; r < Nn; r += RB) s += g_emb[(size_t)r * MEMD + c];
    g_partial[b * MEMD + c] = s;
}

__global__ void k_final(const float* __restrict__ fc2w, const float* __restrict__ fc2b,
                        float* __restrict__ out, int Nn) {
    __shared__ float tm[MEMD];
    int c = threadIdx.x;
    if (c < MEMD) {
        float s = 0.f;
        for (int b = 0; b < RB; b++) s += g_partial[b * MEMD + c];
        tm[c] = tanhf(s / (float)(Nn - 1));
    }
    __syncthreads();
    if (c == 0) {
        float l0 = fc2b[0], l1 = fc2b[1];
        for (int i = 0; i < MEMD; i++) {
            l0 += tm[i] * fc2w[i * 2 + 0];
            l1 += tm[i] * fc2w[i * 2 + 1];
        }
        float mx = fmaxf(l0, l1);
        float e0 = expf(l0 - mx), e1 = expf(l1 - mx);
        float inv = 1.f / (e0 + e1);
        out[0] = e0 * inv;
        out[1] = e1 * inv;
    }
}

// ---------------- host orchestration ----------------
extern "C" void kernel_launch(void* const* d_in, const int* in_sizes, int n_in,
                              void* d_out, int out_size) {
    const float* node_features = (const float*)d_in[0];
    const float* memory        = (const float*)d_in[1];
    const float* last_update   = (const float*)d_in[2];
    const float* timestamps    = (const float*)d_in[3];
    const float* edge_features = (const float*)d_in[4];
    const float* neighbor_ts   = (const float*)d_in[5];
    const float* time_w        = (const float*)d_in[6];
    const float* time_b        = (const float*)d_in[7];
    const float* gru_Wi        = (const float*)d_in[8];
    const float* gru_Wh        = (const float*)d_in[9];
    const float* gru_bi        = (const float*)d_in[10];
    const float* gru_bh        = (const float*)d_in[11];
    const float* Wq            = (const float*)d_in[12];
    const float* Wk            = (const float*)d_in[13];
    const float* Wv            = (const float*)d_in[14];
    const float* W1            = (const float*)d_in[15];
    const float* b1            = (const float*)d_in[16];
    const float* W2            = (const float*)d_in[17];
    const float* b2            = (const float*)d_in[18];
    const float* fc2_w         = (const float*)d_in[19];
    const float* fc2_b         = (const float*)d_in[20];
    const int*   sources       = (const int*)d_in[21];
    const int*   destinations  = (const int*)d_in[22];
    const int*   neighbor_idx  = (const int*)d_in[23];

    int N = in_sizes[0] / FEATD;
    int E = in_sizes[3];
    int MtRows = NPAD / 128;

    static int s_attr_done = 0;
    if (!s_attr_done) {
        cudaFuncSetAttribute(k_gemm1, cudaFuncAttributeMaxDynamicSharedMemorySize, SM_TOT);
        s_attr_done = 1;
    }

    __nv_bfloat16 *pMh, *pMemh, *pHagg, *pT1h, *pWtb, *pQKVb, *pGIb, *pGHb;
    __nv_bfloat16 *pWih, *pWhh, *pQh, *pBVh, *pW1h, *pW2h;
    float *pAggF, *pEmb;
    cudaGetSymbolAddress((void**)&pMh,   g_Mh);
    cudaGetSymbolAddress((void**)&pMemh, g_memh);
    cudaGetSymbolAddress((void**)&pHagg, g_hagg);
    cudaGetSymbolAddress((void**)&pT1h,  g_t1h);
    cudaGetSymbolAddress((void**)&pWtb,  g_wtb);
    cudaGetSymbolAddress((void**)&pQKVb, g_QKVb);
    cudaGetSymbolAddress((void**)&pGIb,  g_GIb);
    cudaGetSymbolAddress((void**)&pGHb,  g_GHb);
    cudaGetSymbolAddress((void**)&pWih,  g_BWih);
    cudaGetSymbolAddress((void**)&pWhh,  g_BWhh);
    cudaGetSymbolAddress((void**)&pQh,   g_BQh);
    cudaGetSymbolAddress((void**)&pBVh,  g_BVh);
    cudaGetSymbolAddress((void**)&pW1h,  g_BW1h);
    cudaGetSymbolAddress((void**)&pW2h,  g_BW2h);
    cudaGetSymbolAddress((void**)&pAggF, g_aggF);
    cudaGetSymbolAddress((void**)&pEmb,  g_emb);

    // GI GEMM at my-index 3 (ncu -s 5)
    k_prep_wi_init<<<(KP_M * NP_G + 255) / 256, 256>>>(gru_Wi, N);
    k_scatter<<<(E + 255) / 256, 256>>>(sources, destinations, E);
    k_build_m<<<NPAD, 128>>>(memory, last_update, timestamps, edge_features,
                             time_w, time_b, sources, destinations, N, E);
    k_gemm1<<<dim3(5, MtRows), 256, SM_TOT>>>(pMh, KP_M, pWih, NP_G,
                                              gru_bi, nullptr, pGIb, G3,
                                              N, G3, KP_M, 0, 0);
    k_memconv<<<(NPAD * KP_S + 255) / 256, 256>>>(memory, N);
    k_prep_wh<<<(KP_S * NP_G + 255) / 256, 256>>>(gru_Wh);
    k_gemm1<<<dim3(5, MtRows), 256, SM_TOT>>>(pMemh, KP_S, pWhh, NP_G,
                                              gru_bh, nullptr, pGHb, G3,
                                              N, G3, KP_S, 0, 0);
    k_gate<<<(NPAD * KP_S + 255) / 256, 256>>>(memory, node_features, N);

    // extended QKV = h @ [Wq1|Wk1|Wv1|Wc] -> bf16
    k_prep_qkv<<<(KP_S * NP_Q + 255) / 256, 256>>>(Wq, Wk, Wv);
    k_gemm1<<<dim3(6, MtRows), 256, SM_TOT>>>(pHagg, KP_H, pQh, NP_Q,
                                              nullptr, nullptr, pQKVb, NP_Q,
                                              N, NP_Q, KP_S, 0, 0);

    // attention
    k_prep_qconst<<<1, 256>>>(Wq, Wk, time_b);
    k_prep_bv<<<(WT_K * 256 + 255) / 256, 256>>>(Wv);
    k_attn<<<NPAD, 128>>>(neighbor_idx, neighbor_ts, time_w, time_b,
                          timestamps, N, E);
    // agg = aggF + wt @ Wv2blk -> bf16 into hagg cols 192..383
    k_gemm1<<<dim3(2, MtRows), 256, SM_TOT>>>(pWtb, WT_K, pBVh, 256,
                                              nullptr, pAggF, pHagg + 192, KP_H,
                                              NPAD, KP_S, WT_K, 1, 0);

    // MLP: t1h = bf16(relu(hagg @ W1cat + b1)); emb = t1 @ W2 + b2
    k_prep_w1<<<(KP_H * NP_S + 255) / 256, 256>>>(W1);
    k_prep_w2<<<(KP_S * NP_S + 255) / 256, 256>>>(W2);
    k_gemm1<<<dim3(2, MtRows), 256, SM_TOT>>>(pHagg, KP_H, pW1h, NP_S,
                                              b1, nullptr, pT1h, KP_S,
                                              N, MEMD, KP_H, 0, 1);
    k_gemm1<<<dim3(2, MtRows), 256, SM_TOT>>>(pT1h, KP_S, pW2h, NP_S,
                                              b2, pEmb, nullptr, 0, N, MEMD, KP_S, 0, 0);

    // classifier head
    k_reduce1<<<RB, 192>>>(N);
    k_final<<<1, 192>>>(fc2_w, fc2_b, (float*)d_out, N);
}